// round 2
// baseline (speedup 1.0000x reference)
#include <cuda_runtime.h>
#include <math.h>

// ---------------- problem constants ----------------
constexpr int Nn  = 50000;
constexpr int Ee  = 800000;
constexpr int ET  = Ee + Nn;      // + self loops
constexpr int RNA = 645;
constexpr int SSd = 6;
constexpr int Fin = RNA + SSd;    // 651
constexpr int H   = 128;
constexpr int Hh  = 64;
constexpr int G   = 200;
constexpr float EPS = 1e-5f;

// ---------------- device scratch (no allocations allowed) ----------------
__device__ float g_tmp  [Nn * H];
__device__ float g_h    [Nn * H];
__device__ float g_hres [Nn * H];
__device__ float g_xw   [Nn * H];
__device__ float g_y    [Nn * H];
__device__ float g_gnout[Nn * H];
__device__ float g_h1   [Nn * H];
__device__ float g_h2   [Nn * H];
__device__ float g_as   [Nn];
__device__ float g_ad   [Nn];
__device__ float g_t64  [Nn * Hh];
__device__ float g_fc1o [Nn * Hh];
__device__ int   g_deg  [Nn];
__device__ int   g_fill [Nn];
__device__ int   g_rowptr[Nn + 1];
__device__ int   g_csrc [ET];
__device__ float g_gsum [G * H];
__device__ float g_gvar [G * H];
__device__ float g_mean [G * H];
__device__ float g_istd [G * H];
__device__ int   g_cnt  [G];

// ---------------- small utility kernels ----------------
__global__ void k_zero_f(float* p, int n) {
    for (int i = blockIdx.x * blockDim.x + threadIdx.x; i < n; i += gridDim.x * blockDim.x)
        p[i] = 0.f;
}
__global__ void k_zero_i(int* p, int n) {
    for (int i = blockIdx.x * blockDim.x + threadIdx.x; i < n; i += gridDim.x * blockDim.x)
        p[i] = 0;
}

// ---------------- CSR build ----------------
__global__ void k_hist(const int* __restrict__ ei, int* __restrict__ deg) {
    int i = blockIdx.x * blockDim.x + threadIdx.x;
    if (i >= ET) return;
    int dst = (i < Ee) ? ei[Ee + i] : (i - Ee);
    atomicAdd(&deg[dst], 1);
}

__global__ void k_scan(const int* __restrict__ deg, int* __restrict__ rowptr) {
    __shared__ int sm[1024];
    int t = threadIdx.x;
    const int per = (Nn + 1023) / 1024;
    int b0 = t * per;
    int b1 = min(b0 + per, Nn);
    int loc = 0;
    for (int i = b0; i < b1; ++i) loc += deg[i];
    sm[t] = loc;
    __syncthreads();
    for (int off = 1; off < 1024; off <<= 1) {
        int v = (t >= off) ? sm[t - off] : 0;
        __syncthreads();
        sm[t] += v;
        __syncthreads();
    }
    int run = (t == 0) ? 0 : sm[t - 1];
    for (int i = b0; i < b1; ++i) { rowptr[i] = run; run += deg[i]; }
    if (t == 0) rowptr[Nn] = sm[1023];
}

__global__ void k_scatter(const int* __restrict__ ei, const int* __restrict__ rowptr,
                          int* __restrict__ fill, int* __restrict__ csrc) {
    int i = blockIdx.x * blockDim.x + threadIdx.x;
    if (i >= ET) return;
    int src = (i < Ee) ? ei[i]      : (i - Ee);
    int dst = (i < Ee) ? ei[Ee + i] : (i - Ee);
    int pos = rowptr[dst] + atomicAdd(&fill[dst], 1);
    csrc[pos] = src;
}

// ---------------- SGEMM: C[M,Ncols] = concat(A0,A1)[M,Ktot] * B[Ktot,Ncols] + bias ----------------
template <int BM, int BN, int BK, int TM, int TN>
__global__ void __launch_bounds__((BM / TM) * (BN / TN))
k_sgemm(const float* __restrict__ A0, int K0,
        const float* __restrict__ A1,
        const float* __restrict__ B, const float* __restrict__ bias,
        float* __restrict__ C, int M, int Ktot, int Ncols) {
    constexpr int NT = (BM / TM) * (BN / TN);
    __shared__ float As[BK][BM];
    __shared__ float Bs[BK][BN];

    const int tid = threadIdx.x;
    const int tx  = tid % (BN / TN);
    const int ty  = tid / (BN / TN);
    const int rowBase = blockIdx.x * BM;
    const int colBase = blockIdx.y * BN;
    const int K1 = Ktot - K0;

    float acc[TM][TN];
#pragma unroll
    for (int i = 0; i < TM; ++i)
#pragma unroll
        for (int j = 0; j < TN; ++j) acc[i][j] = 0.f;

    for (int k0 = 0; k0 < Ktot; k0 += BK) {
        // load A tile (transposed into smem)
        for (int i = tid / BK; i < BM; i += NT / BK) {
            int m = rowBase + i;
            int k = k0 + (tid % BK);
            float val = 0.f;
            if (m < M && k < Ktot)
                val = (k < K0) ? A0[(size_t)m * K0 + k]
                               : A1[(size_t)m * K1 + (k - K0)];
            As[tid % BK][i] = val;
        }
        // load B tile
        for (int i = tid / BN; i < BK; i += NT / BN) {
            int k = k0 + i;
            int n = colBase + (tid % BN);
            Bs[i][tid % BN] = (k < Ktot) ? B[(size_t)k * Ncols + n] : 0.f;
        }
        __syncthreads();
#pragma unroll
        for (int kk = 0; kk < BK; ++kk) {
            float ra[TM], rb[TN];
#pragma unroll
            for (int i = 0; i < TM; ++i) ra[i] = As[kk][ty * TM + i];
#pragma unroll
            for (int j = 0; j < TN; ++j) rb[j] = Bs[kk][tx * TN + j];
#pragma unroll
            for (int i = 0; i < TM; ++i)
#pragma unroll
                for (int j = 0; j < TN; ++j) acc[i][j] += ra[i] * rb[j];
        }
        __syncthreads();
    }
#pragma unroll
    for (int i = 0; i < TM; ++i) {
        int m = rowBase + ty * TM + i;
        if (m >= M) continue;
#pragma unroll
        for (int j = 0; j < TN; ++j) {
            int n = colBase + tx * TN + j;
            float v = acc[i][j] + (bias ? bias[n] : 0.f);
            C[(size_t)m * Ncols + n] = v;
        }
    }
}

// ---------------- LayerNorm + ReLU (warp per row) ----------------
template <int HH>
__global__ void k_ln_relu(const float* __restrict__ in, float* __restrict__ out,
                          float* __restrict__ out2,
                          const float* __restrict__ g, const float* __restrict__ b) {
    int w = (blockIdx.x * blockDim.x + threadIdx.x) >> 5;
    if (w >= Nn) return;
    int lane = threadIdx.x & 31;
    constexpr int V = HH / 32;
    float v[V];
    const float* row = in + (size_t)w * HH;
    float s = 0.f;
#pragma unroll
    for (int j = 0; j < V; ++j) { v[j] = row[lane + 32 * j]; s += v[j]; }
    for (int o = 16; o; o >>= 1) s += __shfl_xor_sync(0xffffffffu, s, o);
    float mean = s * (1.f / HH);
    float var = 0.f;
#pragma unroll
    for (int j = 0; j < V; ++j) { float d = v[j] - mean; var += d * d; }
    for (int o = 16; o; o >>= 1) var += __shfl_xor_sync(0xffffffffu, var, o);
    var *= (1.f / HH);
    float is = rsqrtf(var + EPS);
#pragma unroll
    for (int j = 0; j < V; ++j) {
        int c = lane + 32 * j;
        float o_ = (v[j] - mean) * is * g[c] + b[c];
        o_ = fmaxf(o_, 0.f);
        out[(size_t)w * HH + c] = o_;
        if (out2) out2[(size_t)w * HH + c] = o_;
    }
}

// ---------------- attention dot products (warp per row) ----------------
__global__ void k_dots(const float* __restrict__ xw, const float* __restrict__ a_src,
                       const float* __restrict__ a_dst,
                       float* __restrict__ as_, float* __restrict__ ad_) {
    int w = (blockIdx.x * blockDim.x + threadIdx.x) >> 5;
    if (w >= Nn) return;
    int lane = threadIdx.x & 31;
    float s1 = 0.f, s2 = 0.f;
#pragma unroll
    for (int j = 0; j < 4; ++j) {
        int c = lane + 32 * j;
        float v = xw[(size_t)w * H + c];
        s1 += v * a_src[c];
        s2 += v * a_dst[c];
    }
    for (int o = 16; o; o >>= 1) {
        s1 += __shfl_xor_sync(0xffffffffu, s1, o);
        s2 += __shfl_xor_sync(0xffffffffu, s2, o);
    }
    if (lane == 0) { as_[w] = s1; ad_[w] = s2; }
}

// ---------------- GAT aggregate (warp per dst node) ----------------
__device__ __forceinline__ float lrelu(float x) { return x > 0.f ? x : 0.2f * x; }

__global__ void k_agg(const int* __restrict__ rowptr, const int* __restrict__ csrc,
                      const float* __restrict__ as_, const float* __restrict__ ad_,
                      const float* __restrict__ xw, const float* __restrict__ bias,
                      float* __restrict__ y) {
    int w = (blockIdx.x * blockDim.x + threadIdx.x) >> 5;
    if (w >= Nn) return;
    int lane = threadIdx.x & 31;
    int s0 = rowptr[w], s1 = rowptr[w + 1];
    float adn = ad_[w];

    float m = -1e30f;
    for (int i = s0 + lane; i < s1; i += 32)
        m = fmaxf(m, lrelu(as_[csrc[i]] + adn));
    for (int o = 16; o; o >>= 1) m = fmaxf(m, __shfl_xor_sync(0xffffffffu, m, o));

    float s = 0.f;
    for (int i = s0 + lane; i < s1; i += 32)
        s += __expf(lrelu(as_[csrc[i]] + adn) - m);
    for (int o = 16; o; o >>= 1) s += __shfl_xor_sync(0xffffffffu, s, o);
    float inv = 1.f / (s + 1e-16f);

    float4 acc = make_float4(0.f, 0.f, 0.f, 0.f);
    for (int i = s0; i < s1; ++i) {
        int src = csrc[i];
        float al = __expf(lrelu(as_[src] + adn) - m) * inv;
        const float4 v = *reinterpret_cast<const float4*>(&xw[(size_t)src * H + lane * 4]);
        acc.x += al * v.x; acc.y += al * v.y; acc.z += al * v.z; acc.w += al * v.w;
    }
    const float4 bv = *reinterpret_cast<const float4*>(&bias[lane * 4]);
    float4 o = make_float4(acc.x + bv.x, acc.y + bv.y, acc.z + bv.z, acc.w + bv.w);
    *reinterpret_cast<float4*>(&y[(size_t)w * H + lane * 4]) = o;
}

// ---------------- GraphNorm ----------------
__global__ void k_gcount(const int* __restrict__ batch, int* __restrict__ cnt) {
    int i = blockIdx.x * blockDim.x + threadIdx.x;
    if (i < Nn) atomicAdd(&cnt[batch[i]], 1);
}

// sum per (group, col) with run-length local accumulation (batch is sorted)
__global__ void k_gn_pass1(const float* __restrict__ y, const int* __restrict__ batch,
                           float* __restrict__ gsum) {
    int col  = threadIdx.x & (H - 1);
    int half = threadIdx.x >> 7;
    int r0 = blockIdx.x * 64 + half * 32;
    int r1 = min(r0 + 32, Nn);
    float acc = 0.f; int cur = -1;
    for (int r = r0; r < r1; ++r) {
        int gg = batch[r];
        if (gg != cur) {
            if (cur >= 0) atomicAdd(&gsum[cur * H + col], acc);
            acc = 0.f; cur = gg;
        }
        acc += y[(size_t)r * H + col];
    }
    if (cur >= 0) atomicAdd(&gsum[cur * H + col], acc);
}

__global__ void k_gn_mean(const float* __restrict__ gsum, const int* __restrict__ cnt,
                          float* __restrict__ mean) {
    int i = blockIdx.x * blockDim.x + threadIdx.x;
    if (i >= G * H) return;
    float c = fmaxf((float)cnt[i / H], 1.f);
    mean[i] = gsum[i] / c;
}

__global__ void k_gn_pass2(const float* __restrict__ y, const int* __restrict__ batch,
                           const float* __restrict__ mean, const float* __restrict__ ms,
                           float* __restrict__ gnout, float* __restrict__ gvar) {
    int col  = threadIdx.x & (H - 1);
    int half = threadIdx.x >> 7;
    int r0 = blockIdx.x * 64 + half * 32;
    int r1 = min(r0 + 32, Nn);
    float msv = ms[col];
    float acc = 0.f; int cur = -1; float mval = 0.f;
    for (int r = r0; r < r1; ++r) {
        int gg = batch[r];
        if (gg != cur) {
            if (cur >= 0) atomicAdd(&gvar[cur * H + col], acc);
            acc = 0.f; cur = gg;
            mval = mean[gg * H + col];
        }
        float o = y[(size_t)r * H + col] - msv * mval;
        gnout[(size_t)r * H + col] = o;
        acc += o * o;
    }
    if (cur >= 0) atomicAdd(&gvar[cur * H + col], acc);
}

__global__ void k_gn_istd(const float* __restrict__ gvar, const int* __restrict__ cnt,
                          float* __restrict__ istd) {
    int i = blockIdx.x * blockDim.x + threadIdx.x;
    if (i >= G * H) return;
    float c = fmaxf((float)cnt[i / H], 1.f);
    istd[i] = rsqrtf(gvar[i] / c + EPS);
}

__global__ void k_gn_pass3(const float* __restrict__ gnout, const int* __restrict__ batch,
                           const float* __restrict__ istd,
                           const float* __restrict__ w, const float* __restrict__ b,
                           const float* __restrict__ res, float* __restrict__ out) {
    int i = blockIdx.x * blockDim.x + threadIdx.x;
    if (i >= Nn * H) return;
    int row = i >> 7;
    int col = i & (H - 1);
    int gg = batch[row];
    float v = w[col] * gnout[i] * istd[gg * H + col] + b[col];
    v = fmaxf(v, 0.f);                // relu(graphnorm(...))
    if (res) v += res[i];             // residual AFTER relu (h2 = h + h_res)
    out[i] = v;
}

// ---------------- gate combine ----------------
__global__ void k_gate(const float* __restrict__ pre, const float* __restrict__ h1,
                       const float* __restrict__ h2, float* __restrict__ out) {
    int i = blockIdx.x * blockDim.x + threadIdx.x;
    if (i >= Nn * H) return;
    float t = pre[i];
    float s = 1.f / (1.f + __expf(-t));
    out[i] = s * h1[i] + (1.f - s) * h2[i];
}

// ---------------- final fc2 (warp per row, H=64 -> 1) ----------------
__global__ void k_fc2(const float* __restrict__ x, const float* __restrict__ w,
                      const float* __restrict__ b, float* __restrict__ out) {
    int r = (blockIdx.x * blockDim.x + threadIdx.x) >> 5;
    if (r >= Nn) return;
    int lane = threadIdx.x & 31;
    float s = x[(size_t)r * Hh + lane] * w[lane] + x[(size_t)r * Hh + lane + 32] * w[lane + 32];
    for (int o = 16; o; o >>= 1) s += __shfl_xor_sync(0xffffffffu, s, o);
    if (lane == 0) out[r] = s + b[0];
}

// =====================================================================
extern "C" void kernel_launch(void* const* d_in, const int* in_sizes, int n_in,
                              void* d_out, int out_size) {
    const float* rna    = (const float*)d_in[0];
    const float* ss     = (const float*)d_in[1];
    const int*   ei     = (const int*)  d_in[2];
    const int*   batch  = (const int*)  d_in[3];
    const float* W_fuse = (const float*)d_in[4];
    const float* b_fuse = (const float*)d_in[5];
    const float* ln1_g  = (const float*)d_in[6];
    const float* ln1_b  = (const float*)d_in[7];
    const float* W_gat  = (const float*)d_in[8];
    const float* attS   = (const float*)d_in[9];
    const float* attD   = (const float*)d_in[10];
    const float* b_gat  = (const float*)d_in[11];
    const float* gn_w   = (const float*)d_in[12];
    const float* gn_b   = (const float*)d_in[13];
    const float* gn_ms  = (const float*)d_in[14];
    const float* W_gate = (const float*)d_in[15];
    const float* b_gate = (const float*)d_in[16];
    const float* W_head = (const float*)d_in[17];
    const float* b_head = (const float*)d_in[18];
    const float* ln2_g  = (const float*)d_in[19];
    const float* ln2_b  = (const float*)d_in[20];
    const float* W_fc1  = (const float*)d_in[21];
    const float* b_fc1  = (const float*)d_in[22];
    const float* ln3_g  = (const float*)d_in[23];
    const float* ln3_b  = (const float*)d_in[24];
    const float* W_fc2  = (const float*)d_in[25];
    const float* b_fc2  = (const float*)d_in[26];
    float* out = (float*)d_out;

    // scratch symbol addresses (host code runs once at capture; replays reuse graph)
    float *tmp, *h, *hres, *xw, *y, *gnout, *h1, *h2, *as_, *ad_, *t64, *fc1o;
    float *gsum, *gvar, *mean, *istd;
    int *deg, *fill, *rowptr, *csrc, *cnt;
    cudaGetSymbolAddress((void**)&tmp,   g_tmp);
    cudaGetSymbolAddress((void**)&h,     g_h);
    cudaGetSymbolAddress((void**)&hres,  g_hres);
    cudaGetSymbolAddress((void**)&xw,    g_xw);
    cudaGetSymbolAddress((void**)&y,     g_y);
    cudaGetSymbolAddress((void**)&gnout, g_gnout);
    cudaGetSymbolAddress((void**)&h1,    g_h1);
    cudaGetSymbolAddress((void**)&h2,    g_h2);
    cudaGetSymbolAddress((void**)&as_,   g_as);
    cudaGetSymbolAddress((void**)&ad_,   g_ad);
    cudaGetSymbolAddress((void**)&t64,   g_t64);
    cudaGetSymbolAddress((void**)&fc1o,  g_fc1o);
    cudaGetSymbolAddress((void**)&deg,   g_deg);
    cudaGetSymbolAddress((void**)&fill,  g_fill);
    cudaGetSymbolAddress((void**)&rowptr,g_rowptr);
    cudaGetSymbolAddress((void**)&csrc,  g_csrc);
    cudaGetSymbolAddress((void**)&gsum,  g_gsum);
    cudaGetSymbolAddress((void**)&gvar,  g_gvar);
    cudaGetSymbolAddress((void**)&mean,  g_mean);
    cudaGetSymbolAddress((void**)&istd,  g_istd);
    cudaGetSymbolAddress((void**)&cnt,   g_cnt);

    const int TPB = 256;
    const int gRowBlocks = (Nn + 127) / 128;             // 391
    const int gWarpRows  = (Nn * 32 + TPB - 1) / TPB;    // warp-per-row grids
    const int gElems     = (Nn * H + TPB - 1) / TPB;
    const int gEdges     = (ET + TPB - 1) / TPB;
    const int gGN        = (Nn + 63) / 64;               // 64 rows/block
    const int gGH        = (G * H + TPB - 1) / TPB;

    // ---- CSR build (same every call; cheap) ----
    k_zero_i<<<(Nn + TPB - 1) / TPB, TPB>>>(deg, Nn);
    k_zero_i<<<(Nn + TPB - 1) / TPB, TPB>>>(fill, Nn);
    k_hist<<<gEdges, TPB>>>(ei, deg);
    k_scan<<<1, 1024>>>(deg, rowptr);
    k_scatter<<<gEdges, TPB>>>(ei, rowptr, fill, csrc);

    // ---- fuse: concat(rna, ss) @ W_fuse + b -> LN1 -> ReLU ----
    k_sgemm<128, 128, 8, 8, 8><<<dim3(gRowBlocks, 1), 256>>>(
        rna, RNA, ss, W_fuse, b_fuse, tmp, Nn, Fin, H);
    k_ln_relu<128><<<gWarpRows, TPB>>>(tmp, h, hres, ln1_g, ln1_b);

    // ---- GAT layer helper sequence (done twice) ----
    for (int layer = 0; layer < 2; ++layer) {
        const float* xin = (layer == 0) ? h : h1;
        float* dst       = (layer == 0) ? h1 : h2;
        const float* res = (layer == 0) ? nullptr : hres;

        k_sgemm<128, 128, 8, 8, 8><<<dim3(gRowBlocks, 1), 256>>>(
            xin, H, nullptr, W_gat, nullptr, xw, Nn, H, H);
        k_dots<<<gWarpRows, TPB>>>(xw, attS, attD, as_, ad_);
        k_agg<<<gWarpRows, TPB>>>(rowptr, csrc, as_, ad_, xw, b_gat, y);

        k_zero_f<<<gGH, TPB>>>(gsum, G * H);
        k_zero_f<<<gGH, TPB>>>(gvar, G * H);
        k_zero_i<<<1, 256>>>(cnt, G);
        k_gcount<<<(Nn + TPB - 1) / TPB, TPB>>>(batch, cnt);
        k_gn_pass1<<<gGN, 256>>>(y, batch, gsum);
        k_gn_mean<<<gGH, TPB>>>(gsum, cnt, mean);
        k_gn_pass2<<<gGN, 256>>>(y, batch, mean, gn_ms, gnout, gvar);
        k_gn_istd<<<gGH, TPB>>>(gvar, cnt, istd);
        k_gn_pass3<<<gElems, TPB>>>(gnout, batch, istd, gn_w, gn_b, res, dst);
    }

    // ---- gate: sigmoid(concat(h1,h2) @ W_gate + b); h = g*h1 + (1-g)*h2 ----
    k_sgemm<128, 128, 8, 8, 8><<<dim3(gRowBlocks, 1), 256>>>(
        h1, H, h2, W_gate, b_gate, tmp, Nn, 2 * H, H);
    k_gate<<<gElems, TPB>>>(tmp, h1, h2, h);

    // ---- head: h @ W_head + b -> LN2 -> ReLU ----
    k_sgemm<128, 128, 8, 8, 8><<<dim3(gRowBlocks, 1), 256>>>(
        h, H, nullptr, W_head, b_head, tmp, Nn, H, H);
    k_ln_relu<128><<<gWarpRows, TPB>>>(tmp, h, nullptr, ln2_g, ln2_b);

    // ---- fc1: h @ W_fc1 + b -> LN3 -> ReLU ----
    k_sgemm<128, 64, 8, 8, 4><<<dim3(gRowBlocks, 1), 256>>>(
        h, H, nullptr, W_fc1, b_fc1, t64, Nn, H, Hh);
    k_ln_relu<64><<<gWarpRows, TPB>>>(t64, fc1o, nullptr, ln3_g, ln3_b);

    // ---- fc2: fc1o @ W_fc2 + b -> out[N] ----
    k_fc2<<<gWarpRows, TPB>>>(fc1o, W_fc2, b_fc2, out);
}

// round 3
// speedup vs baseline: 2.4580x; 2.4580x over previous
#include <cuda_runtime.h>
#include <math.h>

// ---------------- problem constants ----------------
constexpr int Nn  = 50000;
constexpr int Ee  = 800000;
constexpr int ET  = Ee + Nn;      // + self loops
constexpr int RNA = 645;
constexpr int SSd = 6;
constexpr int Fin = RNA + SSd;    // 651
constexpr int H   = 128;
constexpr int Hh  = 64;
constexpr int G   = 200;
constexpr float EPS = 1e-5f;

// ---------------- device scratch (no allocations allowed) ----------------
__device__ float g_tmp  [Nn * H];
__device__ float g_h    [Nn * H];
__device__ float g_hres [Nn * H];
__device__ float g_xw   [Nn * H];
__device__ float g_y    [Nn * H];
__device__ float g_gnout[Nn * H];
__device__ float g_h1   [Nn * H];
__device__ float g_h2   [Nn * H];
__device__ float g_as   [Nn];
__device__ float g_ad   [Nn];
__device__ float g_t64  [Nn * Hh];
__device__ float g_fc1o [Nn * Hh];
__device__ int   g_deg  [Nn];
__device__ int   g_fill [Nn];
__device__ int   g_rowptr[Nn + 1];
__device__ int   g_csrc [ET];
__device__ int   g_bsum [256];
__device__ float g_gsum [G * H];
__device__ float g_gvar [G * H];
__device__ float g_mean [G * H];
__device__ float g_istd [G * H];
__device__ int   g_cnt  [G];

// ---------------- small utility kernels ----------------
__global__ void k_zero_f(float* p, int n) {
    for (int i = blockIdx.x * blockDim.x + threadIdx.x; i < n; i += gridDim.x * blockDim.x)
        p[i] = 0.f;
}
__global__ void k_zero_i(int* p, int n) {
    for (int i = blockIdx.x * blockDim.x + threadIdx.x; i < n; i += gridDim.x * blockDim.x)
        p[i] = 0;
}

// ---------------- CSR build ----------------
__global__ void k_hist(const int* __restrict__ ei, int* __restrict__ deg) {
    int i = blockIdx.x * blockDim.x + threadIdx.x;
    if (i >= ET) return;
    int dst = (i < Ee) ? ei[Ee + i] : (i - Ee);
    atomicAdd(&deg[dst], 1);
}

// multi-block scan: pass 1 (per-block exclusive scan + block sums)
__global__ void k_scan1(const int* __restrict__ deg, int* __restrict__ rowptr,
                        int* __restrict__ bsum) {
    __shared__ int sm[256];
    int tx = threadIdx.x;
    int i = blockIdx.x * 256 + tx;
    int v = (i < Nn) ? deg[i] : 0;
    sm[tx] = v;
    __syncthreads();
    for (int off = 1; off < 256; off <<= 1) {
        int t = (tx >= off) ? sm[tx - off] : 0;
        __syncthreads();
        sm[tx] += t;
        __syncthreads();
    }
    if (i < Nn) rowptr[i] = sm[tx] - v;          // exclusive within block
    if (tx == 255) bsum[blockIdx.x] = sm[255];
}

// pass 2: exclusive scan of block sums (one block)
__global__ void k_scan2(int* __restrict__ bsum, int nblk) {
    __shared__ int sm[256];
    int tx = threadIdx.x;
    int v = (tx < nblk) ? bsum[tx] : 0;
    sm[tx] = v;
    __syncthreads();
    for (int off = 1; off < 256; off <<= 1) {
        int t = (tx >= off) ? sm[tx - off] : 0;
        __syncthreads();
        sm[tx] += t;
        __syncthreads();
    }
    if (tx < nblk) bsum[tx] = sm[tx] - v;        // exclusive block offsets
}

// pass 3: add block offsets
__global__ void k_scan3(int* __restrict__ rowptr, const int* __restrict__ bsum) {
    int i = blockIdx.x * blockDim.x + threadIdx.x;
    if (i < Nn) rowptr[i] += bsum[i >> 8];
    if (i == 0) rowptr[Nn] = ET;
}

__global__ void k_scatter(const int* __restrict__ ei, const int* __restrict__ rowptr,
                          int* __restrict__ fill, int* __restrict__ csrc) {
    int i = blockIdx.x * blockDim.x + threadIdx.x;
    if (i >= ET) return;
    int src = (i < Ee) ? ei[i]      : (i - Ee);
    int dst = (i < Ee) ? ei[Ee + i] : (i - Ee);
    int pos = rowptr[dst] + atomicAdd(&fill[dst], 1);
    csrc[pos] = src;
}

// ---------------- tf32 helpers ----------------
__device__ __forceinline__ void split_tf32(float x, unsigned& hi, unsigned& lo) {
    unsigned h;
    asm("cvt.rna.tf32.f32 %0, %1;" : "=r"(h) : "f"(x));
    float l = x - __uint_as_float(h);
    unsigned lw;
    asm("cvt.rna.tf32.f32 %0, %1;" : "=r"(lw) : "f"(l));
    hi = h; lo = lw;
}

__device__ __forceinline__ void mma_tf32(float* c, const unsigned* a, const unsigned* b) {
    asm volatile(
        "mma.sync.aligned.m16n8k8.row.col.f32.tf32.tf32.f32 "
        "{%0,%1,%2,%3}, {%4,%5,%6,%7}, {%8,%9}, {%0,%1,%2,%3};"
        : "+f"(c[0]), "+f"(c[1]), "+f"(c[2]), "+f"(c[3])
        : "r"(a[0]), "r"(a[1]), "r"(a[2]), "r"(a[3]), "r"(b[0]), "r"(b[1]));
}

__device__ __forceinline__ void cpa16(float* dst, const float* src, bool pred) {
    unsigned d = (unsigned)__cvta_generic_to_shared(dst);
    int sz = pred ? 16 : 0;
    asm volatile("cp.async.cg.shared.global [%0], [%1], 16, %2;" :: "r"(d), "l"(src), "r"(sz));
}
__device__ __forceinline__ void cpa4(float* dst, const float* src, bool pred) {
    unsigned d = (unsigned)__cvta_generic_to_shared(dst);
    int sz = pred ? 4 : 0;
    asm volatile("cp.async.ca.shared.global [%0], [%1], 4, %2;" :: "r"(d), "l"(src), "r"(sz));
}
__device__ __forceinline__ void cpa_commit() {
    asm volatile("cp.async.commit_group;");
}
template <int NN>
__device__ __forceinline__ void cpa_wait() {
    asm volatile("cp.async.wait_group %0;" :: "n"(NN));
}

// ---------------- tensor-core GEMM (tf32 x3, fp32-accurate) ----------------
// C[M,Ncols] = concat(A0[:,0:K0], A1[:,K0:Ktot]) @ B[Ktot,Ncols] (+bias / epilogue)
// EPI: 0 = bias add, 1 = gate (sigmoid combine of e1/e2)
template <int BN, int EPI, bool SCALAR_A>
__global__ void __launch_bounds__(256)
k_mma(const float* __restrict__ A0, int K0,
      const float* __restrict__ A1,
      const float* __restrict__ B,
      const float* __restrict__ bias,
      float* __restrict__ C, int M, int Ktot, int Ncols,
      const float* __restrict__ e1, const float* __restrict__ e2) {
    constexpr int BM = 128, BK = 16;
    constexpr int ASTR = BK + 4;      // 20: conflict-free fragment reads
    constexpr int BSTR = BN + 8;      // conflict-free fragment reads
    constexpr int WCOL = BN / 32;     // 4 (BN=128) or 2 (BN=64)
    constexpr int WROW = 8 / WCOL;    // 2 or 4
    constexpr int TMW  = BM / WROW;   // 64 or 32
    constexpr int MT   = TMW / 16;    // 4 or 2

    __shared__ float As[2][BM * ASTR];
    __shared__ float Bs[2][BK * BSTR];

    const int tid  = threadIdx.x;
    const int wid  = tid >> 5;
    const int lane = tid & 31;
    const int wr   = wid / WCOL;
    const int wc   = wid % WCOL;
    const int rowBase = blockIdx.x * BM;
    const int K1 = Ktot - K0;

    float acc[MT][4][4];
#pragma unroll
    for (int a = 0; a < MT; ++a)
#pragma unroll
        for (int b = 0; b < 4; ++b)
#pragma unroll
            for (int cc = 0; cc < 4; ++cc) acc[a][b][cc] = 0.f;

    const int T = (Ktot + BK - 1) / BK;

    // ---- tile loader ----
    auto loadTile = [&](int t, int st) {
        int k0 = t * BK;
        if (SCALAR_A) {
#pragma unroll
            for (int i = 0; i < 8; ++i) {
                int e = tid + i * 256;          // 0..2047
                int r = e >> 4, kk = e & 15;
                int m = rowBase + r, k = k0 + kk;
                bool p = (m < M) && (k < Ktot);
                const float* src = A0;
                if (p) src = (k < K0) ? (A0 + (size_t)m * K0 + k)
                                      : (A1 + (size_t)m * K1 + (k - K0));
                cpa4(&As[st][r * ASTR + kk], src, p);
            }
        } else {
#pragma unroll
            for (int i = 0; i < 2; ++i) {
                int e = tid + i * 256;          // 0..511
                int r = e >> 2, kk = (e & 3) * 4;
                int m = rowBase + r, k = k0 + kk;
                bool p = (m < M) && (k < Ktot);
                const float* src = A0;
                if (p) src = (k < K0) ? (A0 + (size_t)m * K0 + k)
                                      : (A1 + (size_t)m * K1 + (k - K0));
                cpa16(&As[st][r * ASTR + kk], src, p);
            }
        }
        constexpr int NB4 = BK * BN / 4;        // 512 or 256
#pragma unroll
        for (int e = 0; e < NB4; e += 256) {
            int idx = e + tid;
            int r = idx / (BN / 4);
            int c = (idx % (BN / 4)) * 4;
            int k = k0 + r;
            bool p = (k < Ktot);
            const float* src = B + (size_t)(p ? k : 0) * Ncols + c;
            cpa16(&Bs[st][r * BSTR + c], src, p);
        }
        cpa_commit();
    };

    // ---- main pipeline ----
    loadTile(0, 0);
    for (int t = 0; t < T; ++t) {
        int st = t & 1;
        if (t + 1 < T) {
            loadTile(t + 1, st ^ 1);
            cpa_wait<1>();
        } else {
            cpa_wait<0>();
        }
        __syncthreads();

#pragma unroll
        for (int ks = 0; ks < 2; ++ks) {
            int kb = ks * 8;
            // B fragments for all 4 n-tiles
            unsigned bhi[4][2], blo[4][2];
#pragma unroll
            for (int nt = 0; nt < 4; ++nt) {
                int col = wc * 32 + nt * 8 + (lane >> 2);
                int bk  = kb + (lane & 3);
                split_tf32(Bs[st][bk * BSTR + col],       bhi[nt][0], blo[nt][0]);
                split_tf32(Bs[st][(bk + 4) * BSTR + col], bhi[nt][1], blo[nt][1]);
            }
#pragma unroll
            for (int mt = 0; mt < MT; ++mt) {
                int r = wr * TMW + mt * 16 + (lane >> 2);
                int c = kb + (lane & 3);
                unsigned ahi[4], alo[4];
                split_tf32(As[st][r * ASTR + c],             ahi[0], alo[0]);
                split_tf32(As[st][(r + 8) * ASTR + c],       ahi[1], alo[1]);
                split_tf32(As[st][r * ASTR + c + 4],         ahi[2], alo[2]);
                split_tf32(As[st][(r + 8) * ASTR + c + 4],   ahi[3], alo[3]);
#pragma unroll
                for (int nt = 0; nt < 4; ++nt) {
                    mma_tf32(acc[mt][nt], ahi, bhi[nt]);
                    mma_tf32(acc[mt][nt], ahi, blo[nt]);
                    mma_tf32(acc[mt][nt], alo, bhi[nt]);
                }
            }
        }
        __syncthreads();
    }

    // ---- epilogue ----
#pragma unroll
    for (int mt = 0; mt < MT; ++mt) {
        int r0 = rowBase + wr * TMW + mt * 16 + (lane >> 2);
#pragma unroll
        for (int nt = 0; nt < 4; ++nt) {
            int c = wc * 32 + nt * 8 + (lane & 3) * 2;
            float bv0 = bias ? bias[c]     : 0.f;
            float bv1 = bias ? bias[c + 1] : 0.f;
#pragma unroll
            for (int hrow = 0; hrow < 2; ++hrow) {
                int r = r0 + hrow * 8;
                if (r >= M) continue;
                float v0 = acc[mt][nt][hrow * 2 + 0] + bv0;
                float v1 = acc[mt][nt][hrow * 2 + 1] + bv1;
                size_t idx = (size_t)r * Ncols + c;
                if (EPI == 1) {
                    float s0 = 1.f / (1.f + __expf(-v0));
                    float s1 = 1.f / (1.f + __expf(-v1));
                    v0 = s0 * e1[idx]     + (1.f - s0) * e2[idx];
                    v1 = s1 * e1[idx + 1] + (1.f - s1) * e2[idx + 1];
                }
                *reinterpret_cast<float2*>(&C[idx]) = make_float2(v0, v1);
            }
        }
    }
}

// ---------------- LayerNorm + ReLU (warp per row) ----------------
template <int HH>
__global__ void k_ln_relu(const float* __restrict__ in, float* __restrict__ out,
                          float* __restrict__ out2,
                          const float* __restrict__ g, const float* __restrict__ b) {
    int w = (blockIdx.x * blockDim.x + threadIdx.x) >> 5;
    if (w >= Nn) return;
    int lane = threadIdx.x & 31;
    constexpr int V = HH / 32;
    float v[V];
    const float* row = in + (size_t)w * HH;
    float s = 0.f;
#pragma unroll
    for (int j = 0; j < V; ++j) { v[j] = row[lane + 32 * j]; s += v[j]; }
    for (int o = 16; o; o >>= 1) s += __shfl_xor_sync(0xffffffffu, s, o);
    float mean = s * (1.f / HH);
    float var = 0.f;
#pragma unroll
    for (int j = 0; j < V; ++j) { float d = v[j] - mean; var += d * d; }
    for (int o = 16; o; o >>= 1) var += __shfl_xor_sync(0xffffffffu, var, o);
    var *= (1.f / HH);
    float is = rsqrtf(var + EPS);
#pragma unroll
    for (int j = 0; j < V; ++j) {
        int c = lane + 32 * j;
        float o_ = (v[j] - mean) * is * g[c] + b[c];
        o_ = fmaxf(o_, 0.f);
        out[(size_t)w * HH + c] = o_;
        if (out2) out2[(size_t)w * HH + c] = o_;
    }
}

// ---------------- attention dot products (warp per row) ----------------
__global__ void k_dots(const float* __restrict__ xw, const float* __restrict__ a_src,
                       const float* __restrict__ a_dst,
                       float* __restrict__ as_, float* __restrict__ ad_) {
    int w = (blockIdx.x * blockDim.x + threadIdx.x) >> 5;
    if (w >= Nn) return;
    int lane = threadIdx.x & 31;
    float s1 = 0.f, s2 = 0.f;
#pragma unroll
    for (int j = 0; j < 4; ++j) {
        int c = lane + 32 * j;
        float v = xw[(size_t)w * H + c];
        s1 += v * a_src[c];
        s2 += v * a_dst[c];
    }
    for (int o = 16; o; o >>= 1) {
        s1 += __shfl_xor_sync(0xffffffffu, s1, o);
        s2 += __shfl_xor_sync(0xffffffffu, s2, o);
    }
    if (lane == 0) { as_[w] = s1; ad_[w] = s2; }
}

// ---------------- GAT aggregate (warp per dst node) ----------------
__device__ __forceinline__ float lrelu(float x) { return x > 0.f ? x : 0.2f * x; }

__global__ void k_agg(const int* __restrict__ rowptr, const int* __restrict__ csrc,
                      const float* __restrict__ as_, const float* __restrict__ ad_,
                      const float* __restrict__ xw, const float* __restrict__ bias,
                      float* __restrict__ y) {
    int w = (blockIdx.x * blockDim.x + threadIdx.x) >> 5;
    if (w >= Nn) return;
    int lane = threadIdx.x & 31;
    int s0 = rowptr[w], s1 = rowptr[w + 1];
    float adn = ad_[w];

    float m = -1e30f;
    for (int i = s0 + lane; i < s1; i += 32)
        m = fmaxf(m, lrelu(as_[csrc[i]] + adn));
    for (int o = 16; o; o >>= 1) m = fmaxf(m, __shfl_xor_sync(0xffffffffu, m, o));

    float s = 0.f;
    for (int i = s0 + lane; i < s1; i += 32)
        s += __expf(lrelu(as_[csrc[i]] + adn) - m);
    for (int o = 16; o; o >>= 1) s += __shfl_xor_sync(0xffffffffu, s, o);
    float inv = 1.f / (s + 1e-16f);

    float4 acc = make_float4(0.f, 0.f, 0.f, 0.f);
    for (int i = s0; i < s1; ++i) {
        int src = csrc[i];
        float al = __expf(lrelu(as_[src] + adn) - m) * inv;
        const float4 v = *reinterpret_cast<const float4*>(&xw[(size_t)src * H + lane * 4]);
        acc.x += al * v.x; acc.y += al * v.y; acc.z += al * v.z; acc.w += al * v.w;
    }
    const float4 bv = *reinterpret_cast<const float4*>(&bias[lane * 4]);
    float4 o = make_float4(acc.x + bv.x, acc.y + bv.y, acc.z + bv.z, acc.w + bv.w);
    *reinterpret_cast<float4*>(&y[(size_t)w * H + lane * 4]) = o;
}

// ---------------- GraphNorm ----------------
__global__ void k_gcount(const int* __restrict__ batch, int* __restrict__ cnt) {
    int i = blockIdx.x * blockDim.x + threadIdx.x;
    if (i < Nn) atomicAdd(&cnt[batch[i]], 1);
}

__global__ void k_gn_pass1(const float* __restrict__ y, const int* __restrict__ batch,
                           float* __restrict__ gsum) {
    int col  = threadIdx.x & (H - 1);
    int half = threadIdx.x >> 7;
    int r0 = blockIdx.x * 64 + half * 32;
    int r1 = min(r0 + 32, Nn);
    float acc = 0.f; int cur = -1;
    for (int r = r0; r < r1; ++r) {
        int gg = batch[r];
        if (gg != cur) {
            if (cur >= 0) atomicAdd(&gsum[cur * H + col], acc);
            acc = 0.f; cur = gg;
        }
        acc += y[(size_t)r * H + col];
    }
    if (cur >= 0) atomicAdd(&gsum[cur * H + col], acc);
}

__global__ void k_gn_mean(const float* __restrict__ gsum, const int* __restrict__ cnt,
                          float* __restrict__ mean) {
    int i = blockIdx.x * blockDim.x + threadIdx.x;
    if (i >= G * H) return;
    float c = fmaxf((float)cnt[i / H], 1.f);
    mean[i] = gsum[i] / c;
}

__global__ void k_gn_pass2(const float* __restrict__ y, const int* __restrict__ batch,
                           const float* __restrict__ mean, const float* __restrict__ ms,
                           float* __restrict__ gnout, float* __restrict__ gvar) {
    int col  = threadIdx.x & (H - 1);
    int half = threadIdx.x >> 7;
    int r0 = blockIdx.x * 64 + half * 32;
    int r1 = min(r0 + 32, Nn);
    float msv = ms[col];
    float acc = 0.f; int cur = -1; float mval = 0.f;
    for (int r = r0; r < r1; ++r) {
        int gg = batch[r];
        if (gg != cur) {
            if (cur >= 0) atomicAdd(&gvar[cur * H + col], acc);
            acc = 0.f; cur = gg;
            mval = mean[gg * H + col];
        }
        float o = y[(size_t)r * H + col] - msv * mval;
        gnout[(size_t)r * H + col] = o;
        acc += o * o;
    }
    if (cur >= 0) atomicAdd(&gvar[cur * H + col], acc);
}

__global__ void k_gn_istd(const float* __restrict__ gvar, const int* __restrict__ cnt,
                          float* __restrict__ istd) {
    int i = blockIdx.x * blockDim.x + threadIdx.x;
    if (i >= G * H) return;
    float c = fmaxf((float)cnt[i / H], 1.f);
    istd[i] = rsqrtf(gvar[i] / c + EPS);
}

__global__ void k_gn_pass3(const float* __restrict__ gnout, const int* __restrict__ batch,
                           const float* __restrict__ istd,
                           const float* __restrict__ w, const float* __restrict__ b,
                           const float* __restrict__ res, float* __restrict__ out) {
    int i = blockIdx.x * blockDim.x + threadIdx.x;
    if (i >= Nn * H) return;
    int row = i >> 7;
    int col = i & (H - 1);
    int gg = batch[row];
    float v = w[col] * gnout[i] * istd[gg * H + col] + b[col];
    v = fmaxf(v, 0.f);
    if (res) v += res[i];
    out[i] = v;
}

// ---------------- final fc2 (warp per row, 64 -> 1) ----------------
__global__ void k_fc2(const float* __restrict__ x, const float* __restrict__ w,
                      const float* __restrict__ b, float* __restrict__ out) {
    int r = (blockIdx.x * blockDim.x + threadIdx.x) >> 5;
    if (r >= Nn) return;
    int lane = threadIdx.x & 31;
    float s = x[(size_t)r * Hh + lane] * w[lane] + x[(size_t)r * Hh + lane + 32] * w[lane + 32];
    for (int o = 16; o; o >>= 1) s += __shfl_xor_sync(0xffffffffu, s, o);
    if (lane == 0) out[r] = s + b[0];
}

// =====================================================================
extern "C" void kernel_launch(void* const* d_in, const int* in_sizes, int n_in,
                              void* d_out, int out_size) {
    const float* rna    = (const float*)d_in[0];
    const float* ss     = (const float*)d_in[1];
    const int*   ei     = (const int*)  d_in[2];
    const int*   batch  = (const int*)  d_in[3];
    const float* W_fuse = (const float*)d_in[4];
    const float* b_fuse = (const float*)d_in[5];
    const float* ln1_g  = (const float*)d_in[6];
    const float* ln1_b  = (const float*)d_in[7];
    const float* W_gat  = (const float*)d_in[8];
    const float* attS   = (const float*)d_in[9];
    const float* attD   = (const float*)d_in[10];
    const float* b_gat  = (const float*)d_in[11];
    const float* gn_w   = (const float*)d_in[12];
    const float* gn_b   = (const float*)d_in[13];
    const float* gn_ms  = (const float*)d_in[14];
    const float* W_gate = (const float*)d_in[15];
    const float* b_gate = (const float*)d_in[16];
    const float* W_head = (const float*)d_in[17];
    const float* b_head = (const float*)d_in[18];
    const float* ln2_g  = (const float*)d_in[19];
    const float* ln2_b  = (const float*)d_in[20];
    const float* W_fc1  = (const float*)d_in[21];
    const float* b_fc1  = (const float*)d_in[22];
    const float* ln3_g  = (const float*)d_in[23];
    const float* ln3_b  = (const float*)d_in[24];
    const float* W_fc2  = (const float*)d_in[25];
    const float* b_fc2  = (const float*)d_in[26];
    float* out = (float*)d_out;

    float *tmp, *h, *hres, *xw, *y, *gnout, *h1, *h2, *as_, *ad_, *t64, *fc1o;
    float *gsum, *gvar, *mean, *istd;
    int *deg, *fill, *rowptr, *csrc, *cnt, *bsum;
    cudaGetSymbolAddress((void**)&tmp,   g_tmp);
    cudaGetSymbolAddress((void**)&h,     g_h);
    cudaGetSymbolAddress((void**)&hres,  g_hres);
    cudaGetSymbolAddress((void**)&xw,    g_xw);
    cudaGetSymbolAddress((void**)&y,     g_y);
    cudaGetSymbolAddress((void**)&gnout, g_gnout);
    cudaGetSymbolAddress((void**)&h1,    g_h1);
    cudaGetSymbolAddress((void**)&h2,    g_h2);
    cudaGetSymbolAddress((void**)&as_,   g_as);
    cudaGetSymbolAddress((void**)&ad_,   g_ad);
    cudaGetSymbolAddress((void**)&t64,   g_t64);
    cudaGetSymbolAddress((void**)&fc1o,  g_fc1o);
    cudaGetSymbolAddress((void**)&deg,   g_deg);
    cudaGetSymbolAddress((void**)&fill,  g_fill);
    cudaGetSymbolAddress((void**)&rowptr,g_rowptr);
    cudaGetSymbolAddress((void**)&csrc,  g_csrc);
    cudaGetSymbolAddress((void**)&bsum,  g_bsum);
    cudaGetSymbolAddress((void**)&gsum,  g_gsum);
    cudaGetSymbolAddress((void**)&gvar,  g_gvar);
    cudaGetSymbolAddress((void**)&mean,  g_mean);
    cudaGetSymbolAddress((void**)&istd,  g_istd);
    cudaGetSymbolAddress((void**)&cnt,   g_cnt);

    const int TPB = 256;
    const int gRowBlocks = (Nn + 127) / 128;             // 391
    const int gWarpRows  = (Nn * 32 + TPB - 1) / TPB;
    const int gElems     = (Nn * H + TPB - 1) / TPB;
    const int gEdges     = (ET + TPB - 1) / TPB;
    const int gGN        = (Nn + 63) / 64;
    const int gGH        = (G * H + TPB - 1) / TPB;
    const int nScanBlk   = (Nn + 255) / 256;             // 196

    // ---- CSR build ----
    k_zero_i<<<(Nn + TPB - 1) / TPB, TPB>>>(deg, Nn);
    k_zero_i<<<(Nn + TPB - 1) / TPB, TPB>>>(fill, Nn);
    k_hist<<<gEdges, TPB>>>(ei, deg);
    k_scan1<<<nScanBlk, 256>>>(deg, rowptr, bsum);
    k_scan2<<<1, 256>>>(bsum, nScanBlk);
    k_scan3<<<(Nn + TPB - 1) / TPB, TPB>>>(rowptr, bsum);
    k_scatter<<<gEdges, TPB>>>(ei, rowptr, fill, csrc);

    // ---- group counts (batch fixed across layers) ----
    k_zero_i<<<1, 256>>>(cnt, G);
    k_gcount<<<(Nn + TPB - 1) / TPB, TPB>>>(batch, cnt);

    // ---- fuse: concat(rna, ss) @ W_fuse + b -> LN1 -> ReLU ----
    k_mma<128, 0, true><<<gRowBlocks, 256>>>(
        rna, RNA, ss, W_fuse, b_fuse, tmp, Nn, Fin, H, nullptr, nullptr);
    k_ln_relu<128><<<gWarpRows, TPB>>>(tmp, h, hres, ln1_g, ln1_b);

    // ---- two GAT + GraphNorm layers ----
    for (int layer = 0; layer < 2; ++layer) {
        const float* xin = (layer == 0) ? h : h1;
        float* dst       = (layer == 0) ? h1 : h2;
        const float* res = (layer == 0) ? nullptr : hres;

        k_mma<128, 0, false><<<gRowBlocks, 256>>>(
            xin, H, nullptr, W_gat, nullptr, xw, Nn, H, H, nullptr, nullptr);
        k_dots<<<gWarpRows, TPB>>>(xw, attS, attD, as_, ad_);
        k_agg<<<gWarpRows, TPB>>>(rowptr, csrc, as_, ad_, xw, b_gat, y);

        k_zero_f<<<gGH, TPB>>>(gsum, G * H);
        k_zero_f<<<gGH, TPB>>>(gvar, G * H);
        k_gn_pass1<<<gGN, 256>>>(y, batch, gsum);
        k_gn_mean<<<gGH, TPB>>>(gsum, cnt, mean);
        k_gn_pass2<<<gGN, 256>>>(y, batch, mean, gn_ms, gnout, gvar);
        k_gn_istd<<<gGH, TPB>>>(gvar, cnt, istd);
        k_gn_pass3<<<gElems, TPB>>>(gnout, batch, istd, gn_w, gn_b, res, dst);
    }

    // ---- gate GEMM with fused sigmoid/combine epilogue -> h ----
    k_mma<128, 1, false><<<gRowBlocks, 256>>>(
        h1, H, h2, W_gate, b_gate, h, Nn, 2 * H, H, h1, h2);

    // ---- head -> LN2 -> ReLU ----
    k_mma<128, 0, false><<<gRowBlocks, 256>>>(
        h, H, nullptr, W_head, b_head, tmp, Nn, H, H, nullptr, nullptr);
    k_ln_relu<128><<<gWarpRows, TPB>>>(tmp, h, nullptr, ln2_g, ln2_b);

    // ---- fc1 -> LN3 -> ReLU ----
    k_mma<64, 0, false><<<gRowBlocks, 256>>>(
        h, H, nullptr, W_fc1, b_fc1, t64, Nn, H, Hh, nullptr, nullptr);
    k_ln_relu<64><<<gWarpRows, TPB>>>(t64, fc1o, nullptr, ln3_g, ln3_b);

    // ---- fc2 ----
    k_fc2<<<gWarpRows, TPB>>>(fc1o, W_fc2, b_fc2, out);
}

// round 4
// speedup vs baseline: 2.8288x; 1.1509x over previous
#include <cuda_runtime.h>
#include <cuda_bf16.h>
#include <math.h>

// ---------------- problem constants ----------------
constexpr int Nn  = 50000;
constexpr int Ee  = 800000;
constexpr int ET  = Ee + Nn;      // + self loops
constexpr int RNA = 645;
constexpr int SSd = 6;
constexpr int Fin = RNA + SSd;    // 651
constexpr int H   = 128;
constexpr int Hh  = 64;
constexpr int G   = 200;
constexpr float EPS = 1e-5f;

// ---------------- device scratch (no allocations allowed) ----------------
__device__ float g_tmp  [Nn * H];
__device__ float g_h    [Nn * H];
__device__ float g_hres [Nn * H];
__device__ float g_xw   [Nn * H];
__device__ float g_y    [Nn * H];
__device__ float g_gnout[Nn * H];
__device__ float g_h1   [Nn * H];
__device__ float g_h2   [Nn * H];
__device__ float g_as   [Nn];
__device__ float g_ad   [Nn];
__device__ float g_t64  [Nn * Hh];
__device__ float g_fc1o [Nn * Hh];
__device__ int   g_deg  [Nn];
__device__ int   g_fill [Nn];
__device__ int   g_rowptr[Nn + 1];
__device__ int   g_csrc [ET];
__device__ int   g_bsum [256];
__device__ float g_gsum [G * H];
__device__ float g_gvar [G * H];
__device__ float g_mean [G * H];
__device__ float g_istd [G * H];
__device__ int   g_cnt  [G];

// ---------------- small utility kernels ----------------
__global__ void k_zero_f(float* p, int n) {
    for (int i = blockIdx.x * blockDim.x + threadIdx.x; i < n; i += gridDim.x * blockDim.x)
        p[i] = 0.f;
}
__global__ void k_zero_i(int* p, int n) {
    for (int i = blockIdx.x * blockDim.x + threadIdx.x; i < n; i += gridDim.x * blockDim.x)
        p[i] = 0;
}

// ---------------- CSR build ----------------
__global__ void k_hist(const int* __restrict__ ei, int* __restrict__ deg) {
    int i = blockIdx.x * blockDim.x + threadIdx.x;
    if (i >= ET) return;
    int dst = (i < Ee) ? ei[Ee + i] : (i - Ee);
    atomicAdd(&deg[dst], 1);
}

__global__ void k_scan1(const int* __restrict__ deg, int* __restrict__ rowptr,
                        int* __restrict__ bsum) {
    __shared__ int sm[256];
    int tx = threadIdx.x;
    int i = blockIdx.x * 256 + tx;
    int v = (i < Nn) ? deg[i] : 0;
    sm[tx] = v;
    __syncthreads();
    for (int off = 1; off < 256; off <<= 1) {
        int t = (tx >= off) ? sm[tx - off] : 0;
        __syncthreads();
        sm[tx] += t;
        __syncthreads();
    }
    if (i < Nn) rowptr[i] = sm[tx] - v;
    if (tx == 255) bsum[blockIdx.x] = sm[255];
}

__global__ void k_scan2(int* __restrict__ bsum, int nblk) {
    __shared__ int sm[256];
    int tx = threadIdx.x;
    int v = (tx < nblk) ? bsum[tx] : 0;
    sm[tx] = v;
    __syncthreads();
    for (int off = 1; off < 256; off <<= 1) {
        int t = (tx >= off) ? sm[tx - off] : 0;
        __syncthreads();
        sm[tx] += t;
        __syncthreads();
    }
    if (tx < nblk) bsum[tx] = sm[tx] - v;
}

__global__ void k_scan3(int* __restrict__ rowptr, const int* __restrict__ bsum) {
    int i = blockIdx.x * blockDim.x + threadIdx.x;
    if (i < Nn) rowptr[i] += bsum[i >> 8];
    if (i == 0) rowptr[Nn] = ET;
}

__global__ void k_scatter(const int* __restrict__ ei, const int* __restrict__ rowptr,
                          int* __restrict__ fill, int* __restrict__ csrc) {
    int i = blockIdx.x * blockDim.x + threadIdx.x;
    if (i >= ET) return;
    int src = (i < Ee) ? ei[i]      : (i - Ee);
    int dst = (i < Ee) ? ei[Ee + i] : (i - Ee);
    int pos = rowptr[dst] + atomicAdd(&fill[dst], 1);
    csrc[pos] = src;
}

// ---------------- bf16 mma helper ----------------
__device__ __forceinline__ void mma_bf16(float* c, const unsigned* a, const unsigned* b) {
    asm volatile(
        "mma.sync.aligned.m16n8k16.row.col.f32.bf16.bf16.f32 "
        "{%0,%1,%2,%3}, {%4,%5,%6,%7}, {%8,%9}, {%0,%1,%2,%3};"
        : "+f"(c[0]), "+f"(c[1]), "+f"(c[2]), "+f"(c[3])
        : "r"(a[0]), "r"(a[1]), "r"(a[2]), "r"(a[3]), "r"(b[0]), "r"(b[1]));
}

// pack two floats to bf16x2: lo half = x0, hi half = x1
__device__ __forceinline__ unsigned pack_bf16x2(float x0, float x1) {
    unsigned p;
    asm("cvt.rn.bf16x2.f32 %0, %1, %2;" : "=r"(p) : "f"(x1), "f"(x0));
    return p;
}

// ---------------- tensor-core GEMM (bf16 x3 split, ~fp32-accurate) ----------------
// C[M,Ncols] = concat(A0[:,0:K0], A1[:,K0:Ktot]) @ B[Ktot,Ncols] (+bias / epilogue)
// EPI: 0 = bias add, 1 = gate (sigmoid combine of e1/e2)
template <int BN, int EPI, bool SCALAR_A>
__global__ void __launch_bounds__(256)
k_mma(const float* __restrict__ A0, int K0,
      const float* __restrict__ A1,
      const float* __restrict__ B,
      const float* __restrict__ bias,
      float* __restrict__ C, int M, int Ktot, int Ncols,
      const float* __restrict__ e1, const float* __restrict__ e2) {
    constexpr int BM = 128, BK = 32;
    constexpr int KW = 20;                 // 32-bit words per row (16 data + 4 pad)
    constexpr int WCOL = BN / 32;          // 4 (BN=128) / 2 (BN=64)
    constexpr int WROW = 8 / WCOL;
    constexpr int TMW  = BM / WROW;
    constexpr int MT   = TMW / 16;
    constexpr int AELT = BM * BK / 256;    // 16
    constexpr int BELT = BK * BN / 256;    // 16 / 8

    // bf16 hi/lo planes, stored as 32-bit words of 2 k-adjacent bf16
    __shared__ unsigned AsH[BM * KW], AsL[BM * KW];
    __shared__ unsigned BsH[BN * KW], BsL[BN * KW];

    const int tid  = threadIdx.x;
    const int wid  = tid >> 5;
    const int lane = tid & 31;
    const int wr   = wid / WCOL;
    const int wc   = wid % WCOL;
    const int rowBase = blockIdx.x * BM;
    const int K1 = Ktot - K0;

    // A load mapping: row ar, 16 consecutive k starting at ac
    const int ar = tid >> 1, ac = (tid & 1) * 16;
    const int am = rowBase + ar;
    // B load mapping: column bn, BELT consecutive k starting at bk0
    const int bn  = tid & (BN - 1);
    const int bk0 = (tid / BN) * BELT;

    float aReg[AELT], bReg[BELT];
    float acc[MT][4][4];
#pragma unroll
    for (int a = 0; a < MT; ++a)
#pragma unroll
        for (int b = 0; b < 4; ++b)
#pragma unroll
            for (int cc = 0; cc < 4; ++cc) acc[a][b][cc] = 0.f;

    const int T = (Ktot + BK - 1) / BK;

    auto gload = [&](int t) {
        const int k0 = t * BK;
        if (SCALAR_A) {
#pragma unroll
            for (int j = 0; j < AELT; ++j) {
                int k = k0 + ac + j;
                float v = 0.f;
                if (am < M && k < Ktot)
                    v = (k < K0) ? A0[(size_t)am * K0 + k]
                                 : A1[(size_t)am * K1 + (k - K0)];
                aReg[j] = v;
            }
        } else {
#pragma unroll
            for (int j4 = 0; j4 < AELT / 4; ++j4) {
                int k = k0 + ac + j4 * 4;
                float4 v = make_float4(0.f, 0.f, 0.f, 0.f);
                if (am < M) {
                    const float* p = (k < K0) ? (A0 + (size_t)am * K0 + k)
                                              : (A1 + (size_t)am * K1 + (k - K0));
                    v = *reinterpret_cast<const float4*>(p);
                }
                aReg[j4 * 4 + 0] = v.x; aReg[j4 * 4 + 1] = v.y;
                aReg[j4 * 4 + 2] = v.z; aReg[j4 * 4 + 3] = v.w;
            }
        }
#pragma unroll
        for (int j = 0; j < BELT; ++j) {
            int k = k0 + bk0 + j;
            bReg[j] = (k < Ktot) ? B[(size_t)k * Ncols + bn] : 0.f;
        }
    };

    auto convert = [&]() {
#pragma unroll
        for (int j = 0; j < AELT; j += 2) {
            unsigned ph = pack_bf16x2(aReg[j], aReg[j + 1]);
            float h0 = __uint_as_float(ph << 16);
            float h1 = __uint_as_float(ph & 0xffff0000u);
            unsigned pl = pack_bf16x2(aReg[j] - h0, aReg[j + 1] - h1);
            int wi = ar * KW + ((ac + j) >> 1);
            AsH[wi] = ph; AsL[wi] = pl;
        }
#pragma unroll
        for (int j = 0; j < BELT; j += 2) {
            unsigned ph = pack_bf16x2(bReg[j], bReg[j + 1]);
            float h0 = __uint_as_float(ph << 16);
            float h1 = __uint_as_float(ph & 0xffff0000u);
            unsigned pl = pack_bf16x2(bReg[j] - h0, bReg[j + 1] - h1);
            int wi = bn * KW + ((bk0 + j) >> 1);
            BsH[wi] = ph; BsL[wi] = pl;
        }
    };

    gload(0);
    for (int t = 0; t < T; ++t) {
        __syncthreads();          // previous tile's mma done
        convert();
        __syncthreads();          // planes ready
        if (t + 1 < T) gload(t + 1);

#pragma unroll
        for (int ks = 0; ks < 2; ++ks) {
            unsigned bh[4][2], bl[4][2];
#pragma unroll
            for (int nt = 0; nt < 4; ++nt) {
                int n  = wc * 32 + nt * 8 + (lane >> 2);
                int kw = ks * 8 + (lane & 3);
                bh[nt][0] = BsH[n * KW + kw];     bl[nt][0] = BsL[n * KW + kw];
                bh[nt][1] = BsH[n * KW + kw + 4]; bl[nt][1] = BsL[n * KW + kw + 4];
            }
#pragma unroll
            for (int mt = 0; mt < MT; ++mt) {
                int r  = wr * TMW + mt * 16 + (lane >> 2);
                int kw = ks * 8 + (lane & 3);
                unsigned ah[4], al[4];
                ah[0] = AsH[r * KW + kw];           al[0] = AsL[r * KW + kw];
                ah[1] = AsH[(r + 8) * KW + kw];     al[1] = AsL[(r + 8) * KW + kw];
                ah[2] = AsH[r * KW + kw + 4];       al[2] = AsL[r * KW + kw + 4];
                ah[3] = AsH[(r + 8) * KW + kw + 4]; al[3] = AsL[(r + 8) * KW + kw + 4];
#pragma unroll
                for (int nt = 0; nt < 4; ++nt) {
                    mma_bf16(acc[mt][nt], ah, bh[nt]);
                    mma_bf16(acc[mt][nt], ah, bl[nt]);
                    mma_bf16(acc[mt][nt], al, bh[nt]);
                }
            }
        }
    }

    // ---- epilogue ----
#pragma unroll
    for (int mt = 0; mt < MT; ++mt) {
        int r0 = rowBase + wr * TMW + mt * 16 + (lane >> 2);
#pragma unroll
        for (int nt = 0; nt < 4; ++nt) {
            int c = wc * 32 + nt * 8 + (lane & 3) * 2;
            float bv0 = bias ? bias[c]     : 0.f;
            float bv1 = bias ? bias[c + 1] : 0.f;
#pragma unroll
            for (int hrow = 0; hrow < 2; ++hrow) {
                int r = r0 + hrow * 8;
                if (r >= M) continue;
                float v0 = acc[mt][nt][hrow * 2 + 0] + bv0;
                float v1 = acc[mt][nt][hrow * 2 + 1] + bv1;
                size_t idx = (size_t)r * Ncols + c;
                if (EPI == 1) {
                    float s0 = 1.f / (1.f + __expf(-v0));
                    float s1 = 1.f / (1.f + __expf(-v1));
                    v0 = s0 * e1[idx]     + (1.f - s0) * e2[idx];
                    v1 = s1 * e1[idx + 1] + (1.f - s1) * e2[idx + 1];
                }
                *reinterpret_cast<float2*>(&C[idx]) = make_float2(v0, v1);
            }
        }
    }
}

// ---------------- LayerNorm + ReLU (warp per row) ----------------
template <int HH>
__global__ void k_ln_relu(const float* __restrict__ in, float* __restrict__ out,
                          float* __restrict__ out2,
                          const float* __restrict__ g, const float* __restrict__ b) {
    int w = (blockIdx.x * blockDim.x + threadIdx.x) >> 5;
    if (w >= Nn) return;
    int lane = threadIdx.x & 31;
    constexpr int V = HH / 32;
    float v[V];
    const float* row = in + (size_t)w * HH;
    float s = 0.f;
#pragma unroll
    for (int j = 0; j < V; ++j) { v[j] = row[lane + 32 * j]; s += v[j]; }
    for (int o = 16; o; o >>= 1) s += __shfl_xor_sync(0xffffffffu, s, o);
    float mean = s * (1.f / HH);
    float var = 0.f;
#pragma unroll
    for (int j = 0; j < V; ++j) { float d = v[j] - mean; var += d * d; }
    for (int o = 16; o; o >>= 1) var += __shfl_xor_sync(0xffffffffu, var, o);
    var *= (1.f / HH);
    float is = rsqrtf(var + EPS);
#pragma unroll
    for (int j = 0; j < V; ++j) {
        int c = lane + 32 * j;
        float o_ = (v[j] - mean) * is * g[c] + b[c];
        o_ = fmaxf(o_, 0.f);
        out[(size_t)w * HH + c] = o_;
        if (out2) out2[(size_t)w * HH + c] = o_;
    }
}

// ---------------- attention dot products (warp per row) ----------------
__global__ void k_dots(const float* __restrict__ xw, const float* __restrict__ a_src,
                       const float* __restrict__ a_dst,
                       float* __restrict__ as_, float* __restrict__ ad_) {
    int w = (blockIdx.x * blockDim.x + threadIdx.x) >> 5;
    if (w >= Nn) return;
    int lane = threadIdx.x & 31;
    float s1 = 0.f, s2 = 0.f;
#pragma unroll
    for (int j = 0; j < 4; ++j) {
        int c = lane + 32 * j;
        float v = xw[(size_t)w * H + c];
        s1 += v * a_src[c];
        s2 += v * a_dst[c];
    }
    for (int o = 16; o; o >>= 1) {
        s1 += __shfl_xor_sync(0xffffffffu, s1, o);
        s2 += __shfl_xor_sync(0xffffffffu, s2, o);
    }
    if (lane == 0) { as_[w] = s1; ad_[w] = s2; }
}

// ---------------- GAT aggregate (warp per dst node) ----------------
__device__ __forceinline__ float lrelu(float x) { return x > 0.f ? x : 0.2f * x; }

__global__ void k_agg(const int* __restrict__ rowptr, const int* __restrict__ csrc,
                      const float* __restrict__ as_, const float* __restrict__ ad_,
                      const float* __restrict__ xw, const float* __restrict__ bias,
                      float* __restrict__ y) {
    int w = (blockIdx.x * blockDim.x + threadIdx.x) >> 5;
    if (w >= Nn) return;
    int lane = threadIdx.x & 31;
    int s0 = rowptr[w], s1 = rowptr[w + 1];
    float adn = ad_[w];

    float m = -1e30f;
    for (int i = s0 + lane; i < s1; i += 32)
        m = fmaxf(m, lrelu(as_[csrc[i]] + adn));
    for (int o = 16; o; o >>= 1) m = fmaxf(m, __shfl_xor_sync(0xffffffffu, m, o));

    float s = 0.f;
    for (int i = s0 + lane; i < s1; i += 32)
        s += __expf(lrelu(as_[csrc[i]] + adn) - m);
    for (int o = 16; o; o >>= 1) s += __shfl_xor_sync(0xffffffffu, s, o);
    float inv = 1.f / (s + 1e-16f);

    float4 acc = make_float4(0.f, 0.f, 0.f, 0.f);
    for (int i = s0; i < s1; ++i) {
        int src = csrc[i];
        float al = __expf(lrelu(as_[src] + adn) - m) * inv;
        const float4 v = *reinterpret_cast<const float4*>(&xw[(size_t)src * H + lane * 4]);
        acc.x += al * v.x; acc.y += al * v.y; acc.z += al * v.z; acc.w += al * v.w;
    }
    const float4 bv = *reinterpret_cast<const float4*>(&bias[lane * 4]);
    float4 o = make_float4(acc.x + bv.x, acc.y + bv.y, acc.z + bv.z, acc.w + bv.w);
    *reinterpret_cast<float4*>(&y[(size_t)w * H + lane * 4]) = o;
}

// ---------------- GraphNorm ----------------
__global__ void k_gcount(const int* __restrict__ batch, int* __restrict__ cnt) {
    int i = blockIdx.x * blockDim.x + threadIdx.x;
    if (i < Nn) atomicAdd(&cnt[batch[i]], 1);
}

__global__ void k_gn_pass1(const float* __restrict__ y, const int* __restrict__ batch,
                           float* __restrict__ gsum) {
    int col  = threadIdx.x & (H - 1);
    int half = threadIdx.x >> 7;
    int r0 = blockIdx.x * 64 + half * 32;
    int r1 = min(r0 + 32, Nn);
    float acc = 0.f; int cur = -1;
    for (int r = r0; r < r1; ++r) {
        int gg = batch[r];
        if (gg != cur) {
            if (cur >= 0) atomicAdd(&gsum[cur * H + col], acc);
            acc = 0.f; cur = gg;
        }
        acc += y[(size_t)r * H + col];
    }
    if (cur >= 0) atomicAdd(&gsum[cur * H + col], acc);
}

__global__ void k_gn_mean(const float* __restrict__ gsum, const int* __restrict__ cnt,
                          float* __restrict__ mean) {
    int i = blockIdx.x * blockDim.x + threadIdx.x;
    if (i >= G * H) return;
    float c = fmaxf((float)cnt[i / H], 1.f);
    mean[i] = gsum[i] / c;
}

__global__ void k_gn_pass2(const float* __restrict__ y, const int* __restrict__ batch,
                           const float* __restrict__ mean, const float* __restrict__ ms,
                           float* __restrict__ gnout, float* __restrict__ gvar) {
    int col  = threadIdx.x & (H - 1);
    int half = threadIdx.x >> 7;
    int r0 = blockIdx.x * 64 + half * 32;
    int r1 = min(r0 + 32, Nn);
    float msv = ms[col];
    float acc = 0.f; int cur = -1; float mval = 0.f;
    for (int r = r0; r < r1; ++r) {
        int gg = batch[r];
        if (gg != cur) {
            if (cur >= 0) atomicAdd(&gvar[cur * H + col], acc);
            acc = 0.f; cur = gg;
            mval = mean[gg * H + col];
        }
        float o = y[(size_t)r * H + col] - msv * mval;
        gnout[(size_t)r * H + col] = o;
        acc += o * o;
    }
    if (cur >= 0) atomicAdd(&gvar[cur * H + col], acc);
}

__global__ void k_gn_istd(const float* __restrict__ gvar, const int* __restrict__ cnt,
                          float* __restrict__ istd) {
    int i = blockIdx.x * blockDim.x + threadIdx.x;
    if (i >= G * H) return;
    float c = fmaxf((float)cnt[i / H], 1.f);
    istd[i] = rsqrtf(gvar[i] / c + EPS);
}

__global__ void k_gn_pass3(const float* __restrict__ gnout, const int* __restrict__ batch,
                           const float* __restrict__ istd,
                           const float* __restrict__ w, const float* __restrict__ b,
                           const float* __restrict__ res, float* __restrict__ out) {
    int i = blockIdx.x * blockDim.x + threadIdx.x;
    if (i >= Nn * H) return;
    int row = i >> 7;
    int col = i & (H - 1);
    int gg = batch[row];
    float v = w[col] * gnout[i] * istd[gg * H + col] + b[col];
    v = fmaxf(v, 0.f);
    if (res) v += res[i];
    out[i] = v;
}

// ---------------- final fc2 (warp per row, 64 -> 1) ----------------
__global__ void k_fc2(const float* __restrict__ x, const float* __restrict__ w,
                      const float* __restrict__ b, float* __restrict__ out) {
    int r = (blockIdx.x * blockDim.x + threadIdx.x) >> 5;
    if (r >= Nn) return;
    int lane = threadIdx.x & 31;
    float s = x[(size_t)r * Hh + lane] * w[lane] + x[(size_t)r * Hh + lane + 32] * w[lane + 32];
    for (int o = 16; o; o >>= 1) s += __shfl_xor_sync(0xffffffffu, s, o);
    if (lane == 0) out[r] = s + b[0];
}

// =====================================================================
extern "C" void kernel_launch(void* const* d_in, const int* in_sizes, int n_in,
                              void* d_out, int out_size) {
    const float* rna    = (const float*)d_in[0];
    const float* ss     = (const float*)d_in[1];
    const int*   ei     = (const int*)  d_in[2];
    const int*   batch  = (const int*)  d_in[3];
    const float* W_fuse = (const float*)d_in[4];
    const float* b_fuse = (const float*)d_in[5];
    const float* ln1_g  = (const float*)d_in[6];
    const float* ln1_b  = (const float*)d_in[7];
    const float* W_gat  = (const float*)d_in[8];
    const float* attS   = (const float*)d_in[9];
    const float* attD   = (const float*)d_in[10];
    const float* b_gat  = (const float*)d_in[11];
    const float* gn_w   = (const float*)d_in[12];
    const float* gn_b   = (const float*)d_in[13];
    const float* gn_ms  = (const float*)d_in[14];
    const float* W_gate = (const float*)d_in[15];
    const float* b_gate = (const float*)d_in[16];
    const float* W_head = (const float*)d_in[17];
    const float* b_head = (const float*)d_in[18];
    const float* ln2_g  = (const float*)d_in[19];
    const float* ln2_b  = (const float*)d_in[20];
    const float* W_fc1  = (const float*)d_in[21];
    const float* b_fc1  = (const float*)d_in[22];
    const float* ln3_g  = (const float*)d_in[23];
    const float* ln3_b  = (const float*)d_in[24];
    const float* W_fc2  = (const float*)d_in[25];
    const float* b_fc2  = (const float*)d_in[26];
    float* out = (float*)d_out;

    float *tmp, *h, *hres, *xw, *y, *gnout, *h1, *h2, *as_, *ad_, *t64, *fc1o;
    float *gsum, *gvar, *mean, *istd;
    int *deg, *fill, *rowptr, *csrc, *cnt, *bsum;
    cudaGetSymbolAddress((void**)&tmp,   g_tmp);
    cudaGetSymbolAddress((void**)&h,     g_h);
    cudaGetSymbolAddress((void**)&hres,  g_hres);
    cudaGetSymbolAddress((void**)&xw,    g_xw);
    cudaGetSymbolAddress((void**)&y,     g_y);
    cudaGetSymbolAddress((void**)&gnout, g_gnout);
    cudaGetSymbolAddress((void**)&h1,    g_h1);
    cudaGetSymbolAddress((void**)&h2,    g_h2);
    cudaGetSymbolAddress((void**)&as_,   g_as);
    cudaGetSymbolAddress((void**)&ad_,   g_ad);
    cudaGetSymbolAddress((void**)&t64,   g_t64);
    cudaGetSymbolAddress((void**)&fc1o,  g_fc1o);
    cudaGetSymbolAddress((void**)&deg,   g_deg);
    cudaGetSymbolAddress((void**)&fill,  g_fill);
    cudaGetSymbolAddress((void**)&rowptr,g_rowptr);
    cudaGetSymbolAddress((void**)&csrc,  g_csrc);
    cudaGetSymbolAddress((void**)&bsum,  g_bsum);
    cudaGetSymbolAddress((void**)&gsum,  g_gsum);
    cudaGetSymbolAddress((void**)&gvar,  g_gvar);
    cudaGetSymbolAddress((void**)&mean,  g_mean);
    cudaGetSymbolAddress((void**)&istd,  g_istd);
    cudaGetSymbolAddress((void**)&cnt,   g_cnt);

    const int TPB = 256;
    const int gRowBlocks = (Nn + 127) / 128;             // 391
    const int gWarpRows  = (Nn * 32 + TPB - 1) / TPB;
    const int gElems     = (Nn * H + TPB - 1) / TPB;
    const int gEdges     = (ET + TPB - 1) / TPB;
    const int gGN        = (Nn + 63) / 64;
    const int gGH        = (G * H + TPB - 1) / TPB;
    const int nScanBlk   = (Nn + 255) / 256;             // 196

    // ---- CSR build ----
    k_zero_i<<<(Nn + TPB - 1) / TPB, TPB>>>(deg, Nn);
    k_zero_i<<<(Nn + TPB - 1) / TPB, TPB>>>(fill, Nn);
    k_hist<<<gEdges, TPB>>>(ei, deg);
    k_scan1<<<nScanBlk, 256>>>(deg, rowptr, bsum);
    k_scan2<<<1, 256>>>(bsum, nScanBlk);
    k_scan3<<<(Nn + TPB - 1) / TPB, TPB>>>(rowptr, bsum);
    k_scatter<<<gEdges, TPB>>>(ei, rowptr, fill, csrc);

    // ---- group counts ----
    k_zero_i<<<1, 256>>>(cnt, G);
    k_gcount<<<(Nn + TPB - 1) / TPB, TPB>>>(batch, cnt);

    // ---- fuse: concat(rna, ss) @ W_fuse + b -> LN1 -> ReLU ----
    k_mma<128, 0, true><<<gRowBlocks, 256>>>(
        rna, RNA, ss, W_fuse, b_fuse, tmp, Nn, Fin, H, nullptr, nullptr);
    k_ln_relu<128><<<gWarpRows, TPB>>>(tmp, h, hres, ln1_g, ln1_b);

    // ---- two GAT + GraphNorm layers ----
    for (int layer = 0; layer < 2; ++layer) {
        const float* xin = (layer == 0) ? h : h1;
        float* dst       = (layer == 0) ? h1 : h2;
        const float* res = (layer == 0) ? nullptr : hres;

        k_mma<128, 0, false><<<gRowBlocks, 256>>>(
            xin, H, nullptr, W_gat, nullptr, xw, Nn, H, H, nullptr, nullptr);
        k_dots<<<gWarpRows, TPB>>>(xw, attS, attD, as_, ad_);
        k_agg<<<gWarpRows, TPB>>>(rowptr, csrc, as_, ad_, xw, b_gat, y);

        k_zero_f<<<gGH, TPB>>>(gsum, G * H);
        k_zero_f<<<gGH, TPB>>>(gvar, G * H);
        k_gn_pass1<<<gGN, 256>>>(y, batch, gsum);
        k_gn_mean<<<gGH, TPB>>>(gsum, cnt, mean);
        k_gn_pass2<<<gGN, 256>>>(y, batch, mean, gn_ms, gnout, gvar);
        k_gn_istd<<<gGH, TPB>>>(gvar, cnt, istd);
        k_gn_pass3<<<gElems, TPB>>>(gnout, batch, istd, gn_w, gn_b, res, dst);
    }

    // ---- gate GEMM with fused sigmoid/combine epilogue -> h ----
    k_mma<128, 1, false><<<gRowBlocks, 256>>>(
        h1, H, h2, W_gate, b_gate, h, Nn, 2 * H, H, h1, h2);

    // ---- head -> LN2 -> ReLU ----
    k_mma<128, 0, false><<<gRowBlocks, 256>>>(
        h, H, nullptr, W_head, b_head, tmp, Nn, H, H, nullptr, nullptr);
    k_ln_relu<128><<<gWarpRows, TPB>>>(tmp, h, nullptr, ln2_g, ln2_b);

    // ---- fc1 -> LN3 -> ReLU ----
    k_mma<64, 0, false><<<gRowBlocks, 256>>>(
        h, H, nullptr, W_fc1, b_fc1, t64, Nn, H, Hh, nullptr, nullptr);
    k_ln_relu<64><<<gWarpRows, TPB>>>(t64, fc1o, nullptr, ln3_g, ln3_b);

    // ---- fc2 ----
    k_fc2<<<gWarpRows, TPB>>>(fc1o, W_fc2, b_fc2, out);
}

// round 7
// speedup vs baseline: 3.0210x; 1.0679x over previous
#include <cuda_runtime.h>
#include <cuda_bf16.h>
#include <math.h>

// ---------------- problem constants ----------------
constexpr int Nn  = 50000;
constexpr int Ee  = 800000;
constexpr int ET  = Ee + Nn;      // + self loops
constexpr int RNA = 645;
constexpr int SSd = 6;
constexpr int Fin = RNA + SSd;    // 651
constexpr int H   = 128;
constexpr int G   = 200;
constexpr float EPS = 1e-5f;

constexpr int BUF_STRIDE = 132;
constexpr int DYN_SMEM   = 128 * BUF_STRIDE * 4;   // 67584 B

// ---------------- device scratch ----------------
__device__ float g_h    [Nn * H];
__device__ float g_hres [Nn * H];
__device__ float g_xw   [Nn * H];
__device__ float g_y    [Nn * H];
__device__ float g_h1   [Nn * H];
__device__ float g_h2   [Nn * H];
__device__ float g_as   [Nn];
__device__ float g_ad   [Nn];
__device__ int   g_deg  [Nn];
__device__ int   g_fill [Nn];
__device__ int   g_rowptr[Nn + 1];
__device__ int   g_csrc [ET];
__device__ int   g_bsum [256];
__device__ float g_gsum [G * H];   // sum(y)
__device__ float g_gsq  [G * H];   // sum(y^2)
__device__ float g_kA   [G * H];   // w*istd
__device__ float g_kB   [G * H];   // b - kA*ms*mean
__device__ int   g_cnt  [G];

// ---------------- small utility kernels ----------------
__global__ void k_zero2_f(float* p1, float* p2, int n) {
    int i = blockIdx.x * blockDim.x + threadIdx.x;
    if (i < n) { p1[i] = 0.f; p2[i] = 0.f; }
}
__global__ void k_zero_all(int* deg, int* fill, int* cnt) {
    int i = blockIdx.x * blockDim.x + threadIdx.x;
    if (i < Nn) { deg[i] = 0; fill[i] = 0; }
    if (i < G) cnt[i] = 0;
}

// ---------------- CSR build ----------------
__global__ void k_hist(const int* __restrict__ ei, int* __restrict__ deg) {
    int i = blockIdx.x * blockDim.x + threadIdx.x;
    if (i >= ET) return;
    int dst = (i < Ee) ? ei[Ee + i] : (i - Ee);
    atomicAdd(&deg[dst], 1);
}

__global__ void k_scan1(const int* __restrict__ deg, int* __restrict__ rowptr,
                        int* __restrict__ bsum) {
    __shared__ int sm[256];
    int tx = threadIdx.x;
    int i = blockIdx.x * 256 + tx;
    int v = (i < Nn) ? deg[i] : 0;
    sm[tx] = v;
    __syncthreads();
    for (int off = 1; off < 256; off <<= 1) {
        int t = (tx >= off) ? sm[tx - off] : 0;
        __syncthreads();
        sm[tx] += t;
        __syncthreads();
    }
    if (i < Nn) rowptr[i] = sm[tx] - v;
    if (tx == 255) bsum[blockIdx.x] = sm[255];
}

__global__ void k_scan2(int* __restrict__ bsum, int nblk) {
    __shared__ int sm[256];
    int tx = threadIdx.x;
    int v = (tx < nblk) ? bsum[tx] : 0;
    sm[tx] = v;
    __syncthreads();
    for (int off = 1; off < 256; off <<= 1) {
        int t = (tx >= off) ? sm[tx - off] : 0;
        __syncthreads();
        sm[tx] += t;
        __syncthreads();
    }
    if (tx < nblk) bsum[tx] = sm[tx] - v;
}

__global__ void k_scan3(int* __restrict__ rowptr, const int* __restrict__ bsum) {
    int i = blockIdx.x * blockDim.x + threadIdx.x;
    if (i < Nn) rowptr[i] += bsum[i >> 8];
    if (i == 0) rowptr[Nn] = ET;
}

__global__ void k_scatter(const int* __restrict__ ei, const int* __restrict__ rowptr,
                          int* __restrict__ fill, int* __restrict__ csrc) {
    int i = blockIdx.x * blockDim.x + threadIdx.x;
    if (i >= ET) return;
    int src = (i < Ee) ? ei[i]      : (i - Ee);
    int dst = (i < Ee) ? ei[Ee + i] : (i - Ee);
    int pos = rowptr[dst] + atomicAdd(&fill[dst], 1);
    csrc[pos] = src;
}

__global__ void k_gcount(const int* __restrict__ batch, int* __restrict__ cnt) {
    int i = blockIdx.x * blockDim.x + threadIdx.x;
    if (i < Nn) atomicAdd(&cnt[batch[i]], 1);
}

// ---------------- bf16 mma helpers ----------------
__device__ __forceinline__ void mma_bf16(float* c, const unsigned* a, const unsigned* b) {
    asm volatile(
        "mma.sync.aligned.m16n8k16.row.col.f32.bf16.bf16.f32 "
        "{%0,%1,%2,%3}, {%4,%5,%6,%7}, {%8,%9}, {%0,%1,%2,%3};"
        : "+f"(c[0]), "+f"(c[1]), "+f"(c[2]), "+f"(c[3])
        : "r"(a[0]), "r"(a[1]), "r"(a[2]), "r"(a[3]), "r"(b[0]), "r"(b[1]));
}
__device__ __forceinline__ unsigned pack_bf16x2(float x0, float x1) {
    unsigned p;
    asm("cvt.rn.bf16x2.f32 %0, %1, %2;" : "=r"(p) : "f"(x1), "f"(x0));
    return p;
}
__device__ __forceinline__ void split_pair(float x0, float x1, unsigned& ph, unsigned& pl) {
    ph = pack_bf16x2(x0, x1);
    float h0 = __uint_as_float(ph << 16);
    float h1 = __uint_as_float(ph & 0xffff0000u);
    pl = pack_bf16x2(x0 - h0, x1 - h1);
}

constexpr int KW = 20;   // smem plane words per row (16 data + 4 pad)

// ---------------- standalone tensor-core GEMM ----------------
// EPI 0: bias add -> C.   EPI 3: stage to smem, row-LN+ReLU -> C and C2.
template <int EPI, bool SCALAR_A>
__global__ void __launch_bounds__(256)
k_mma(const float* __restrict__ A0, int K0,
      const float* __restrict__ A1,
      const float* __restrict__ B,
      const float* __restrict__ bias,
      float* __restrict__ C, int M, int Ktot, int Ncols,
      const float* __restrict__ lng, const float* __restrict__ lnb,
      float* __restrict__ C2) {
    constexpr int BM = 128, BN = 128, BK = 32;
    constexpr int AELT = 16, BELT = 16;

    __shared__ unsigned AsH[BM * KW], AsL[BM * KW];
    __shared__ unsigned BsH[BN * KW], BsL[BN * KW];
    extern __shared__ float dbuf[];

    const int tid  = threadIdx.x;
    const int wid  = tid >> 5;
    const int lane = tid & 31;
    const int wr   = wid >> 2;          // 0..1
    const int wc   = wid & 3;           // 0..3
    const int rowBase = blockIdx.x * BM;
    const int K1 = Ktot - K0;

    const int ar = tid >> 1, ac = (tid & 1) * 16;
    const int am = rowBase + ar;
    const int bn  = tid & 127;
    const int bk0 = (tid >> 7) * 16;

    float aReg[AELT], bReg[BELT];
    float acc[4][4][4];
#pragma unroll
    for (int a = 0; a < 4; ++a)
#pragma unroll
        for (int b = 0; b < 4; ++b)
#pragma unroll
            for (int cc = 0; cc < 4; ++cc) acc[a][b][cc] = 0.f;

    const int T = (Ktot + BK - 1) / BK;

    auto gload = [&](int t) {
        const int k0 = t * BK;
        if (SCALAR_A) {
#pragma unroll
            for (int j = 0; j < AELT; ++j) {
                int k = k0 + ac + j;
                float v = 0.f;
                if (am < M && k < Ktot)
                    v = (k < K0) ? A0[(size_t)am * K0 + k]
                                 : A1[(size_t)am * K1 + (k - K0)];
                aReg[j] = v;
            }
        } else {
#pragma unroll
            for (int j4 = 0; j4 < AELT / 4; ++j4) {
                int k = k0 + ac + j4 * 4;
                float4 v = make_float4(0.f, 0.f, 0.f, 0.f);
                if (am < M) {
                    const float* p = (k < K0) ? (A0 + (size_t)am * K0 + k)
                                              : (A1 + (size_t)am * K1 + (k - K0));
                    v = *reinterpret_cast<const float4*>(p);
                }
                aReg[j4 * 4 + 0] = v.x; aReg[j4 * 4 + 1] = v.y;
                aReg[j4 * 4 + 2] = v.z; aReg[j4 * 4 + 3] = v.w;
            }
        }
#pragma unroll
        for (int j = 0; j < BELT; ++j) {
            int k = k0 + bk0 + j;
            bReg[j] = (k < Ktot) ? B[(size_t)k * Ncols + bn] : 0.f;
        }
    };

    auto convert = [&]() {
#pragma unroll
        for (int j = 0; j < AELT; j += 2) {
            unsigned ph, pl;
            split_pair(aReg[j], aReg[j + 1], ph, pl);
            int wi = ar * KW + ((ac + j) >> 1);
            AsH[wi] = ph; AsL[wi] = pl;
        }
#pragma unroll
        for (int j = 0; j < BELT; j += 2) {
            unsigned ph, pl;
            split_pair(bReg[j], bReg[j + 1], ph, pl);
            int wi = bn * KW + ((bk0 + j) >> 1);
            BsH[wi] = ph; BsL[wi] = pl;
        }
    };

    gload(0);
    for (int t = 0; t < T; ++t) {
        __syncthreads();
        convert();
        __syncthreads();
        if (t + 1 < T) gload(t + 1);

#pragma unroll
        for (int ks = 0; ks < 2; ++ks) {
            unsigned bh[4][2], bl[4][2];
#pragma unroll
            for (int nt = 0; nt < 4; ++nt) {
                int n  = wc * 32 + nt * 8 + (lane >> 2);
                int kw = ks * 8 + (lane & 3);
                bh[nt][0] = BsH[n * KW + kw];     bl[nt][0] = BsL[n * KW + kw];
                bh[nt][1] = BsH[n * KW + kw + 4]; bl[nt][1] = BsL[n * KW + kw + 4];
            }
#pragma unroll
            for (int mt = 0; mt < 4; ++mt) {
                int r  = wr * 64 + mt * 16 + (lane >> 2);
                int kw = ks * 8 + (lane & 3);
                unsigned ah[4], al[4];
                ah[0] = AsH[r * KW + kw];           al[0] = AsL[r * KW + kw];
                ah[1] = AsH[(r + 8) * KW + kw];     al[1] = AsL[(r + 8) * KW + kw];
                ah[2] = AsH[r * KW + kw + 4];       al[2] = AsL[r * KW + kw + 4];
                ah[3] = AsH[(r + 8) * KW + kw + 4]; al[3] = AsL[(r + 8) * KW + kw + 4];
#pragma unroll
                for (int nt = 0; nt < 4; ++nt) {
                    mma_bf16(acc[mt][nt], ah, bh[nt]);
                    mma_bf16(acc[mt][nt], ah, bl[nt]);
                    mma_bf16(acc[mt][nt], al, bh[nt]);
                }
            }
        }
    }

    if (EPI == 0) {
#pragma unroll
        for (int mt = 0; mt < 4; ++mt) {
            int r0 = rowBase + wr * 64 + mt * 16 + (lane >> 2);
#pragma unroll
            for (int nt = 0; nt < 4; ++nt) {
                int c = wc * 32 + nt * 8 + (lane & 3) * 2;
                float bv0 = bias ? bias[c]     : 0.f;
                float bv1 = bias ? bias[c + 1] : 0.f;
#pragma unroll
                for (int hrow = 0; hrow < 2; ++hrow) {
                    int r = r0 + hrow * 8;
                    if (r >= M) continue;
                    *reinterpret_cast<float2*>(&C[(size_t)r * Ncols + c]) =
                        make_float2(acc[mt][nt][hrow * 2 + 0] + bv0,
                                    acc[mt][nt][hrow * 2 + 1] + bv1);
                }
            }
        }
    } else {
        // EPI == 3: stage to smem; block-local LN+ReLU; write C and C2
#pragma unroll
        for (int mt = 0; mt < 4; ++mt) {
            int rl = wr * 64 + mt * 16 + (lane >> 2);
#pragma unroll
            for (int nt = 0; nt < 4; ++nt) {
                int c = wc * 32 + nt * 8 + (lane & 3) * 2;
                float bv0 = bias[c], bv1 = bias[c + 1];
#pragma unroll
                for (int hrow = 0; hrow < 2; ++hrow) {
                    int r = rl + hrow * 8;
                    dbuf[r * BUF_STRIDE + c]     = acc[mt][nt][hrow * 2 + 0] + bv0;
                    dbuf[r * BUF_STRIDE + c + 1] = acc[mt][nt][hrow * 2 + 1] + bv1;
                }
            }
        }
        __syncthreads();
#pragma unroll 1
        for (int i = 0; i < 16; ++i) {
            int r = wid * 16 + i;
            int gr = rowBase + r;
            float v[4]; float s = 0.f;
#pragma unroll
            for (int j = 0; j < 4; ++j) { v[j] = dbuf[r * BUF_STRIDE + lane + 32 * j]; s += v[j]; }
            for (int o = 16; o; o >>= 1) s += __shfl_xor_sync(0xffffffffu, s, o);
            float mean = s * (1.f / 128.f);
            float var = 0.f;
#pragma unroll
            for (int j = 0; j < 4; ++j) { float d = v[j] - mean; var += d * d; }
            for (int o = 16; o; o >>= 1) var += __shfl_xor_sync(0xffffffffu, var, o);
            float is = rsqrtf(var * (1.f / 128.f) + EPS);
            if (gr < M) {
#pragma unroll
                for (int j = 0; j < 4; ++j) {
                    int c = lane + 32 * j;
                    float o_ = fmaxf((v[j] - mean) * is * lng[c] + lnb[c], 0.f);
                    C [(size_t)gr * 128 + c] = o_;
                    C2[(size_t)gr * 128 + c] = o_;
                }
            }
        }
    }
}

// ---------------- fused tail: gate GEMM + combine + head + LN2 + fc1 + LN3 + fc2 ----------------
__global__ void __launch_bounds__(256)
k_tail(const float* __restrict__ h1, const float* __restrict__ h2,
       const float* __restrict__ Wg,  const float* __restrict__ bg,
       const float* __restrict__ Wh,  const float* __restrict__ bhd,
       const float* __restrict__ g2,  const float* __restrict__ b2,
       const float* __restrict__ Wf1, const float* __restrict__ bf1,
       const float* __restrict__ g3,  const float* __restrict__ b3,
       const float* __restrict__ Wf2, const float* __restrict__ bf2,
       float* __restrict__ out, int M) {
    __shared__ unsigned AsH[128 * KW], AsL[128 * KW];
    __shared__ unsigned BsH[128 * KW], BsL[128 * KW];
    extern __shared__ float dbuf[];

    const int tid  = threadIdx.x;
    const int wid  = tid >> 5;
    const int lane = tid & 31;
    const int rowBase = blockIdx.x * 128;
    const int ar = tid >> 1, ac = (tid & 1) * 16;
    const int am = rowBase + ar;

    float aReg[16], bReg[16];
    float acc[4][4][4];

    auto convertA = [&]() {
#pragma unroll
        for (int j = 0; j < 16; j += 2) {
            unsigned ph, pl;
            split_pair(aReg[j], aReg[j + 1], ph, pl);
            int wi = ar * KW + ((ac + j) >> 1);
            AsH[wi] = ph; AsL[wi] = pl;
        }
    };

    auto mma128 = [&](int wr, int wc) {
#pragma unroll
        for (int ks = 0; ks < 2; ++ks) {
            unsigned bh[4][2], bl[4][2];
#pragma unroll
            for (int nt = 0; nt < 4; ++nt) {
                int n  = wc * 32 + nt * 8 + (lane >> 2);
                int kw = ks * 8 + (lane & 3);
                bh[nt][0] = BsH[n * KW + kw];     bl[nt][0] = BsL[n * KW + kw];
                bh[nt][1] = BsH[n * KW + kw + 4]; bl[nt][1] = BsL[n * KW + kw + 4];
            }
#pragma unroll
            for (int mt = 0; mt < 4; ++mt) {
                int r  = wr * 64 + mt * 16 + (lane >> 2);
                int kw = ks * 8 + (lane & 3);
                unsigned ah[4], al[4];
                ah[0] = AsH[r * KW + kw];           al[0] = AsL[r * KW + kw];
                ah[1] = AsH[(r + 8) * KW + kw];     al[1] = AsL[(r + 8) * KW + kw];
                ah[2] = AsH[r * KW + kw + 4];       al[2] = AsL[r * KW + kw + 4];
                ah[3] = AsH[(r + 8) * KW + kw + 4]; al[3] = AsL[(r + 8) * KW + kw + 4];
#pragma unroll
                for (int nt = 0; nt < 4; ++nt) {
                    mma_bf16(acc[mt][nt], ah, bh[nt]);
                    mma_bf16(acc[mt][nt], ah, bl[nt]);
                    mma_bf16(acc[mt][nt], al, bh[nt]);
                }
            }
        }
    };

    auto zacc = [&]() {
#pragma unroll
        for (int a = 0; a < 4; ++a)
#pragma unroll
            for (int b = 0; b < 4; ++b)
#pragma unroll
                for (int cc = 0; cc < 4; ++cc) acc[a][b][cc] = 0.f;
    };

    // ================= stage 0: gate GEMM (K=256, N=128) =================
    {
        const int wr = wid >> 2, wc = wid & 3;
        const int bn = tid & 127, bk0 = (tid >> 7) * 16;
        zacc();
        auto gload = [&](int t) {
            const int k0 = t * 32;
#pragma unroll
            for (int j4 = 0; j4 < 4; ++j4) {
                int k = k0 + ac + j4 * 4;
                float4 v = make_float4(0.f, 0.f, 0.f, 0.f);
                if (am < M) {
                    const float* p = (k < 128) ? (h1 + (size_t)am * 128 + k)
                                               : (h2 + (size_t)am * 128 + (k - 128));
                    v = *reinterpret_cast<const float4*>(p);
                }
                aReg[j4 * 4 + 0] = v.x; aReg[j4 * 4 + 1] = v.y;
                aReg[j4 * 4 + 2] = v.z; aReg[j4 * 4 + 3] = v.w;
            }
#pragma unroll
            for (int j = 0; j < 16; ++j)
                bReg[j] = Wg[(size_t)(k0 + bk0 + j) * 128 + bn];
        };
        auto convertB = [&]() {
#pragma unroll
            for (int j = 0; j < 16; j += 2) {
                unsigned ph, pl;
                split_pair(bReg[j], bReg[j + 1], ph, pl);
                int wi = bn * KW + ((bk0 + j) >> 1);
                BsH[wi] = ph; BsL[wi] = pl;
            }
        };
        gload(0);
        for (int t = 0; t < 8; ++t) {
            __syncthreads();
            convertA(); convertB();
            __syncthreads();
            if (t + 1 < 8) gload(t + 1);
            mma128(wr, wc);
        }
        // epilogue: sigmoid gate + combine -> dbuf
#pragma unroll
        for (int mt = 0; mt < 4; ++mt) {
            int rl = wr * 64 + mt * 16 + (lane >> 2);
#pragma unroll
            for (int nt = 0; nt < 4; ++nt) {
                int c = wc * 32 + nt * 8 + (lane & 3) * 2;
#pragma unroll
                for (int hrow = 0; hrow < 2; ++hrow) {
                    int r = rl + hrow * 8;
                    int gr = rowBase + r;
                    float o0 = 0.f, o1 = 0.f;
                    if (gr < M) {
                        size_t idx = (size_t)gr * 128 + c;
                        float v0 = acc[mt][nt][hrow * 2 + 0] + bg[c];
                        float v1 = acc[mt][nt][hrow * 2 + 1] + bg[c + 1];
                        float s0 = 1.f / (1.f + __expf(-v0));
                        float s1 = 1.f / (1.f + __expf(-v1));
                        o0 = s0 * h1[idx]     + (1.f - s0) * h2[idx];
                        o1 = s1 * h1[idx + 1] + (1.f - s1) * h2[idx + 1];
                    }
                    dbuf[r * BUF_STRIDE + c]     = o0;
                    dbuf[r * BUF_STRIDE + c + 1] = o1;
                }
            }
        }
    }

    // ================= stage 1: head GEMM (K=128, N=128), A from dbuf =================
    {
        const int wr = wid >> 2, wc = wid & 3;
        const int bn = tid & 127, bk0 = (tid >> 7) * 16;
        zacc();
        for (int t = 0; t < 4; ++t) {
            const int k0 = t * 32;
            __syncthreads();   // dbuf stable / planes free
#pragma unroll
            for (int j = 0; j < 16; ++j) aReg[j] = dbuf[ar * BUF_STRIDE + k0 + ac + j];
            convertA();
#pragma unroll
            for (int j = 0; j < 16; j += 2) {
                float x0 = Wh[(size_t)(k0 + bk0 + j) * 128 + bn];
                float x1 = Wh[(size_t)(k0 + bk0 + j + 1) * 128 + bn];
                unsigned ph, pl;
                split_pair(x0, x1, ph, pl);
                int wi = bn * KW + ((bk0 + j) >> 1);
                BsH[wi] = ph; BsL[wi] = pl;
            }
            __syncthreads();
            mma128(wr, wc);
        }
        // epilogue -> dbuf (overwrites stage0; all reads already done)
#pragma unroll
        for (int mt = 0; mt < 4; ++mt) {
            int rl = wr * 64 + mt * 16 + (lane >> 2);
#pragma unroll
            for (int nt = 0; nt < 4; ++nt) {
                int c = wc * 32 + nt * 8 + (lane & 3) * 2;
#pragma unroll
                for (int hrow = 0; hrow < 2; ++hrow) {
                    int r = rl + hrow * 8;
                    dbuf[r * BUF_STRIDE + c]     = acc[mt][nt][hrow * 2 + 0] + bhd[c];
                    dbuf[r * BUF_STRIDE + c + 1] = acc[mt][nt][hrow * 2 + 1] + bhd[c + 1];
                }
            }
        }
    }
    __syncthreads();

    // ================= LN2 + ReLU in place =================
#pragma unroll 1
    for (int i = 0; i < 16; ++i) {
        int r = wid * 16 + i;
        float v[4]; float s = 0.f;
#pragma unroll
        for (int j = 0; j < 4; ++j) { v[j] = dbuf[r * BUF_STRIDE + lane + 32 * j]; s += v[j]; }
        for (int o = 16; o; o >>= 1) s += __shfl_xor_sync(0xffffffffu, s, o);
        float mean = s * (1.f / 128.f);
        float var = 0.f;
#pragma unroll
        for (int j = 0; j < 4; ++j) { float d = v[j] - mean; var += d * d; }
        for (int o = 16; o; o >>= 1) var += __shfl_xor_sync(0xffffffffu, var, o);
        float is = rsqrtf(var * (1.f / 128.f) + EPS);
#pragma unroll
        for (int j = 0; j < 4; ++j) {
            int c = lane + 32 * j;
            dbuf[r * BUF_STRIDE + c] = fmaxf((v[j] - mean) * is * g2[c] + b2[c], 0.f);
        }
    }
    __syncthreads();

    // ================= stage 2: fc1 GEMM (K=128, N=64) =================
    {
        const int wr = wid >> 1, wc = wid & 1;      // 4 warp-rows x 2 warp-cols
        const int bn = tid & 63, bk0 = (tid >> 6) * 8;
        zacc();                                     // use acc[0..1][..][..]
        for (int t = 0; t < 4; ++t) {
            const int k0 = t * 32;
            __syncthreads();
#pragma unroll
            for (int j = 0; j < 16; ++j) aReg[j] = dbuf[ar * BUF_STRIDE + k0 + ac + j];
            convertA();
#pragma unroll
            for (int j = 0; j < 8; j += 2) {
                float x0 = Wf1[(size_t)(k0 + bk0 + j) * 64 + bn];
                float x1 = Wf1[(size_t)(k0 + bk0 + j + 1) * 64 + bn];
                unsigned ph, pl;
                split_pair(x0, x1, ph, pl);
                int wi = bn * KW + ((bk0 + j) >> 1);
                BsH[wi] = ph; BsL[wi] = pl;
            }
            __syncthreads();
#pragma unroll
            for (int ks = 0; ks < 2; ++ks) {
                unsigned bh[4][2], bl[4][2];
#pragma unroll
                for (int nt = 0; nt < 4; ++nt) {
                    int n  = wc * 32 + nt * 8 + (lane >> 2);
                    int kw = ks * 8 + (lane & 3);
                    bh[nt][0] = BsH[n * KW + kw];     bl[nt][0] = BsL[n * KW + kw];
                    bh[nt][1] = BsH[n * KW + kw + 4]; bl[nt][1] = BsL[n * KW + kw + 4];
                }
#pragma unroll
                for (int mt = 0; mt < 2; ++mt) {
                    int r  = wr * 32 + mt * 16 + (lane >> 2);
                    int kw = ks * 8 + (lane & 3);
                    unsigned ah[4], al[4];
                    ah[0] = AsH[r * KW + kw];           al[0] = AsL[r * KW + kw];
                    ah[1] = AsH[(r + 8) * KW + kw];     al[1] = AsL[(r + 8) * KW + kw];
                    ah[2] = AsH[r * KW + kw + 4];       al[2] = AsL[r * KW + kw + 4];
                    ah[3] = AsH[(r + 8) * KW + kw + 4]; al[3] = AsL[(r + 8) * KW + kw + 4];
#pragma unroll
                    for (int nt = 0; nt < 4; ++nt) {
                        mma_bf16(acc[mt][nt], ah, bh[nt]);
                        mma_bf16(acc[mt][nt], ah, bl[nt]);
                        mma_bf16(acc[mt][nt], al, bh[nt]);
                    }
                }
            }
        }
        // epilogue -> dbuf stride 68
#pragma unroll
        for (int mt = 0; mt < 2; ++mt) {
            int rl = wr * 32 + mt * 16 + (lane >> 2);
#pragma unroll
            for (int nt = 0; nt < 4; ++nt) {
                int c = wc * 32 + nt * 8 + (lane & 3) * 2;
#pragma unroll
                for (int hrow = 0; hrow < 2; ++hrow) {
                    int r = rl + hrow * 8;
                    dbuf[r * 68 + c]     = acc[mt][nt][hrow * 2 + 0] + bf1[c];
                    dbuf[r * 68 + c + 1] = acc[mt][nt][hrow * 2 + 1] + bf1[c + 1];
                }
            }
        }
    }
    __syncthreads();

    // ================= LN3 + ReLU + fc2 =================
    {
        float w0 = Wf2[lane], w1 = Wf2[lane + 32];
#pragma unroll 1
        for (int i = 0; i < 16; ++i) {
            int r = wid * 16 + i;
            int gr = rowBase + r;
            float x0 = dbuf[r * 68 + lane];
            float x1 = dbuf[r * 68 + lane + 32];
            float s = x0 + x1;
            for (int o = 16; o; o >>= 1) s += __shfl_xor_sync(0xffffffffu, s, o);
            float mean = s * (1.f / 64.f);
            float d0 = x0 - mean, d1 = x1 - mean;
            float var = d0 * d0 + d1 * d1;
            for (int o = 16; o; o >>= 1) var += __shfl_xor_sync(0xffffffffu, var, o);
            float is = rsqrtf(var * (1.f / 64.f) + EPS);
            float n0 = fmaxf(d0 * is * g3[lane]      + b3[lane],      0.f);
            float n1 = fmaxf(d1 * is * g3[lane + 32] + b3[lane + 32], 0.f);
            float dot = n0 * w0 + n1 * w1;
            for (int o = 16; o; o >>= 1) dot += __shfl_xor_sync(0xffffffffu, dot, o);
            if (lane == 0 && gr < M) out[gr] = dot + bf2[0];
        }
    }
}

// ---------------- attention dot products (warp per row) ----------------
__global__ void k_dots(const float* __restrict__ xw, const float* __restrict__ a_src,
                       const float* __restrict__ a_dst,
                       float* __restrict__ as_, float* __restrict__ ad_) {
    int w = (blockIdx.x * blockDim.x + threadIdx.x) >> 5;
    if (w >= Nn) return;
    int lane = threadIdx.x & 31;
    float s1 = 0.f, s2 = 0.f;
#pragma unroll
    for (int j = 0; j < 4; ++j) {
        int c = lane + 32 * j;
        float v = xw[(size_t)w * H + c];
        s1 += v * a_src[c];
        s2 += v * a_dst[c];
    }
    for (int o = 16; o; o >>= 1) {
        s1 += __shfl_xor_sync(0xffffffffu, s1, o);
        s2 += __shfl_xor_sync(0xffffffffu, s2, o);
    }
    if (lane == 0) { as_[w] = s1; ad_[w] = s2; }
}

// ---------------- GAT aggregate (warp per dst node) ----------------
__device__ __forceinline__ float lrelu(float x) { return x > 0.f ? x : 0.2f * x; }

__global__ void k_agg(const int* __restrict__ rowptr, const int* __restrict__ csrc,
                      const float* __restrict__ as_, const float* __restrict__ ad_,
                      const float* __restrict__ xw, const float* __restrict__ bias,
                      float* __restrict__ y) {
    int w = (blockIdx.x * blockDim.x + threadIdx.x) >> 5;
    if (w >= Nn) return;
    int lane = threadIdx.x & 31;
    int s0 = rowptr[w], s1 = rowptr[w + 1];
    float adn = ad_[w];

    float m = -1e30f;
    for (int i = s0 + lane; i < s1; i += 32)
        m = fmaxf(m, lrelu(as_[csrc[i]] + adn));
    for (int o = 16; o; o >>= 1) m = fmaxf(m, __shfl_xor_sync(0xffffffffu, m, o));

    float s = 0.f;
    for (int i = s0 + lane; i < s1; i += 32)
        s += __expf(lrelu(as_[csrc[i]] + adn) - m);
    for (int o = 16; o; o >>= 1) s += __shfl_xor_sync(0xffffffffu, s, o);
    float inv = 1.f / (s + 1e-16f);

    float4 acc = make_float4(0.f, 0.f, 0.f, 0.f);
    for (int i = s0; i < s1; ++i) {
        int src = csrc[i];
        float al = __expf(lrelu(as_[src] + adn) - m) * inv;
        const float4 v = *reinterpret_cast<const float4*>(&xw[(size_t)src * H + lane * 4]);
        acc.x += al * v.x; acc.y += al * v.y; acc.z += al * v.z; acc.w += al * v.w;
    }
    const float4 bv = *reinterpret_cast<const float4*>(&bias[lane * 4]);
    float4 o = make_float4(acc.x + bv.x, acc.y + bv.y, acc.z + bv.z, acc.w + bv.w);
    *reinterpret_cast<float4*>(&y[(size_t)w * H + lane * 4]) = o;
}

// ---------------- GraphNorm: one-pass stats ----------------
__global__ void k_gn_stats(const float* __restrict__ y, const int* __restrict__ batch,
                           float* __restrict__ gsum, float* __restrict__ gsq) {
    int col  = threadIdx.x & (H - 1);
    int half = threadIdx.x >> 7;
    int r0 = blockIdx.x * 64 + half * 32;
    int r1 = min(r0 + 32, Nn);
    float a1 = 0.f, a2 = 0.f; int cur = -1;
    for (int r = r0; r < r1; ++r) {
        int gg = batch[r];
        if (gg != cur) {
            if (cur >= 0) {
                atomicAdd(&gsum[cur * H + col], a1);
                atomicAdd(&gsq [cur * H + col], a2);
            }
            a1 = 0.f; a2 = 0.f; cur = gg;
        }
        float v = y[(size_t)r * H + col];
        a1 += v; a2 += v * v;
    }
    if (cur >= 0) {
        atomicAdd(&gsum[cur * H + col], a1);
        atomicAdd(&gsq [cur * H + col], a2);
    }
}

__global__ void k_gn_fin(const float* __restrict__ gsum, const float* __restrict__ gsq,
                         const int* __restrict__ cnt,
                         const float* __restrict__ w, const float* __restrict__ b,
                         const float* __restrict__ ms,
                         float* __restrict__ kA, float* __restrict__ kB) {
    int i = blockIdx.x * blockDim.x + threadIdx.x;
    if (i >= G * H) return;
    int col = i & (H - 1);
    float c = fmaxf((float)cnt[i >> 7], 1.f);
    float mean = gsum[i] / c;
    float q    = gsq[i] / c;
    float msv  = ms[col];
    float var = q - msv * (2.f - msv) * mean * mean;
    float is = rsqrtf(var + EPS);
    float a = w[col] * is;
    kA[i] = a;
    kB[i] = b[col] - a * msv * mean;
}

__global__ void k_gn_norm(const float* __restrict__ y, const int* __restrict__ batch,
                          const float* __restrict__ kA, const float* __restrict__ kB,
                          const float* __restrict__ res, float* __restrict__ out) {
    int i = blockIdx.x * blockDim.x + threadIdx.x;
    if (i >= Nn * H) return;
    int row = i >> 7;
    int col = i & (H - 1);
    int gi = batch[row] * H + col;
    float v = fmaxf(fmaf(y[i], kA[gi], kB[gi]), 0.f);
    if (res) v += res[i];
    out[i] = v;
}

// =====================================================================
extern "C" void kernel_launch(void* const* d_in, const int* in_sizes, int n_in,
                              void* d_out, int out_size) {
    const float* rna    = (const float*)d_in[0];
    const float* ss     = (const float*)d_in[1];
    const int*   ei     = (const int*)  d_in[2];
    const int*   batch  = (const int*)  d_in[3];
    const float* W_fuse = (const float*)d_in[4];
    const float* b_fuse = (const float*)d_in[5];
    const float* ln1_g  = (const float*)d_in[6];
    const float* ln1_b  = (const float*)d_in[7];
    const float* W_gat  = (const float*)d_in[8];
    const float* attS   = (const float*)d_in[9];
    const float* attD   = (const float*)d_in[10];
    const float* b_gat  = (const float*)d_in[11];
    const float* gn_w   = (const float*)d_in[12];
    const float* gn_b   = (const float*)d_in[13];
    const float* gn_ms  = (const float*)d_in[14];
    const float* W_gate = (const float*)d_in[15];
    const float* b_gate = (const float*)d_in[16];
    const float* W_head = (const float*)d_in[17];
    const float* b_head = (const float*)d_in[18];
    const float* ln2_g  = (const float*)d_in[19];
    const float* ln2_b  = (const float*)d_in[20];
    const float* W_fc1  = (const float*)d_in[21];
    const float* b_fc1  = (const float*)d_in[22];
    const float* ln3_g  = (const float*)d_in[23];
    const float* ln3_b  = (const float*)d_in[24];
    const float* W_fc2  = (const float*)d_in[25];
    const float* b_fc2  = (const float*)d_in[26];
    float* out = (float*)d_out;

    float *h, *hres, *xw, *y, *h1, *h2, *as_, *ad_;
    float *gsum, *gsq, *kA, *kB;
    int *deg, *fill, *rowptr, *csrc, *cnt, *bsum;
    cudaGetSymbolAddress((void**)&h,     g_h);
    cudaGetSymbolAddress((void**)&hres,  g_hres);
    cudaGetSymbolAddress((void**)&xw,    g_xw);
    cudaGetSymbolAddress((void**)&y,     g_y);
    cudaGetSymbolAddress((void**)&h1,    g_h1);
    cudaGetSymbolAddress((void**)&h2,    g_h2);
    cudaGetSymbolAddress((void**)&as_,   g_as);
    cudaGetSymbolAddress((void**)&ad_,   g_ad);
    cudaGetSymbolAddress((void**)&deg,   g_deg);
    cudaGetSymbolAddress((void**)&fill,  g_fill);
    cudaGetSymbolAddress((void**)&rowptr,g_rowptr);
    cudaGetSymbolAddress((void**)&csrc,  g_csrc);
    cudaGetSymbolAddress((void**)&bsum,  g_bsum);
    cudaGetSymbolAddress((void**)&gsum,  g_gsum);
    cudaGetSymbolAddress((void**)&gsq,   g_gsq);
    cudaGetSymbolAddress((void**)&kA,    g_kA);
    cudaGetSymbolAddress((void**)&kB,    g_kB);
    cudaGetSymbolAddress((void**)&cnt,   g_cnt);

    cudaFuncSetAttribute(k_mma<3, true>, cudaFuncAttributeMaxDynamicSharedMemorySize, DYN_SMEM);
    cudaFuncSetAttribute(k_tail,         cudaFuncAttributeMaxDynamicSharedMemorySize, DYN_SMEM);

    const int TPB = 256;
    const int gRowBlocks = (Nn + 127) / 128;             // 391
    const int gWarpRows  = (Nn * 32 + TPB - 1) / TPB;
    const int gElems     = (Nn * H + TPB - 1) / TPB;
    const int gEdges     = (ET + TPB - 1) / TPB;
    const int gGN        = (Nn + 63) / 64;
    const int gGH        = (G * H + TPB - 1) / TPB;
    const int nScanBlk   = (Nn + 255) / 256;             // 196

    // #1..#3: CSR prologue
    k_zero_all<<<(Nn + TPB - 1) / TPB, TPB>>>(deg, fill, cnt);
    k_hist<<<gEdges, TPB>>>(ei, deg);
    k_scan1<<<nScanBlk, 256>>>(deg, rowptr, bsum);
    // #4: fuse GEMM + fused LN1 + ReLU -> h, hres   (profiled slot)
    k_mma<3, true><<<gRowBlocks, 256, DYN_SMEM>>>(
        rna, RNA, ss, W_fuse, b_fuse, h, Nn, Fin, H, ln1_g, ln1_b, hres);
    // CSR rest
    k_scan2<<<1, 256>>>(bsum, nScanBlk);
    k_scan3<<<(Nn + TPB - 1) / TPB, TPB>>>(rowptr, bsum);
    k_scatter<<<gEdges, TPB>>>(ei, rowptr, fill, csrc);
    k_gcount<<<(Nn + TPB - 1) / TPB, TPB>>>(batch, cnt);

    // ---- two GAT + GraphNorm layers ----
    for (int layer = 0; layer < 2; ++layer) {
        const float* xin = (layer == 0) ? h : h1;
        float* dst       = (layer == 0) ? h1 : h2;
        const float* res = (layer == 0) ? nullptr : hres;

        k_mma<0, false><<<gRowBlocks, 256>>>(
            xin, H, nullptr, W_gat, nullptr, xw, Nn, H, H, nullptr, nullptr, nullptr);
        k_dots<<<gWarpRows, TPB>>>(xw, attS, attD, as_, ad_);
        k_agg<<<gWarpRows, TPB>>>(rowptr, csrc, as_, ad_, xw, b_gat, y);

        k_zero2_f<<<gGH, TPB>>>(gsum, gsq, G * H);
        k_gn_stats<<<gGN, 256>>>(y, batch, gsum, gsq);
        k_gn_fin<<<gGH, TPB>>>(gsum, gsq, cnt, gn_w, gn_b, gn_ms, kA, kB);
        k_gn_norm<<<gElems, TPB>>>(y, batch, kA, kB, res, dst);
    }

    // ---- fused tail: gate + combine + head + LN2 + fc1 + LN3 + fc2 ----
    k_tail<<<gRowBlocks, 256, DYN_SMEM>>>(
        h1, h2, W_gate, b_gate, W_head, b_head, ln2_g, ln2_b,
        W_fc1, b_fc1, ln3_g, ln3_b, W_fc2, b_fc2, out, Nn);
}